// round 2
// baseline (speedup 1.0000x reference)
#include <cuda_runtime.h>
#include <cstdint>

// Problem constants (dataset shape is fixed by the reference)
#define NMAX 100000

// ---------------- scratch (static device globals; no allocation) ----------------
__device__ float g_norm_s[NMAX];          // deg_out^-1/2
__device__ float g_norm_d[NMAX];          // deg_in^-1/2
__device__ float g_pre   [NMAX * 64];     // (x*ns)@W1 before aggregation
__device__ float g_agg1  [NMAX * 64];     // segsum(pre[src])
__device__ float g_h1    [NMAX * 64];
__device__ float g_aggH1n[NMAX * 64];     // segsum(h1[src]*ns[src])  (layer-2 pre-GEMM agg)
__device__ float g_agg2  [NMAX * 64];     // (aggH1n @ W2) staging -> then h2
__device__ float g_h2    [NMAX * 64];
__device__ float g_aggJ  [NMAX * 128];    // JK concat aggregation

// ---------------- kernels ----------------

__global__ void zero4_kernel(float* __restrict__ p, int n4) {
    int i = blockIdx.x * blockDim.x + threadIdx.x;
    if (i < n4) reinterpret_cast<float4*>(p)[i] = make_float4(0.f, 0.f, 0.f, 0.f);
}

__global__ void degree_kernel(const int* __restrict__ src, const int* __restrict__ dst,
                              float* __restrict__ dout, float* __restrict__ din, int E) {
    int e = blockIdx.x * blockDim.x + threadIdx.x;
    if (e >= E) return;
    atomicAdd(&dout[src[e]], 1.0f);
    atomicAdd(&din [dst[e]], 1.0f);
}

__global__ void norm_kernel(float* __restrict__ s, float* __restrict__ d, int N) {
    int i = blockIdx.x * blockDim.x + threadIdx.x;
    if (i >= N) return;
    s[i] = rsqrtf(fmaxf(s[i], 1.0f));
    d[i] = rsqrtf(fmaxf(d[i], 1.0f));
}

// out[node, col] = (A[node,:] * (SCALE ? ns[node] : 1)) . W[:, col]  (+ bias if BIAS)
// Block = 256 threads = 4 nodes x 64 cols. W cached in smem, A rows staged in smem.
template<int K, bool SCALE, bool BIAS>
__global__ void gemm64_kernel(const float* __restrict__ A, const float* __restrict__ W,
                              const float* __restrict__ ns, const float* __restrict__ bias,
                              float* __restrict__ out, int N) {
    __shared__ float sW[K * 64];
    __shared__ float sA[4 * K];
    const int tid = threadIdx.x;

    for (int i = tid; i < K * 16; i += 256)
        reinterpret_cast<float4*>(sW)[i] = reinterpret_cast<const float4*>(W)[i];

    const int n0 = blockIdx.x * 4;
    for (int i = tid; i < K; i += 256) {           // K float4s = 4 rows of K floats
        int node = n0 + i / (K / 4);
        float4 v = make_float4(0.f, 0.f, 0.f, 0.f);
        if (node < N) {
            v = reinterpret_cast<const float4*>(A + (size_t)n0 * K)[i];
            if (SCALE) {
                float s = ns[node];
                v.x *= s; v.y *= s; v.z *= s; v.w *= s;
            }
        }
        reinterpret_cast<float4*>(sA)[i] = v;
    }
    __syncthreads();

    const int ln  = tid >> 6;
    const int col = tid & 63;
    float acc = BIAS ? bias[col] : 0.0f;
#pragma unroll
    for (int k = 0; k < K; k++)
        acc = fmaf(sA[ln * K + k], sW[k * 64 + col], acc);

    const int node = n0 + ln;
    if (node < N) out[(size_t)node * 64 + col] = acc;
}

__device__ __forceinline__ void red_add_v4(float* p, float4 v) {
    asm volatile("red.global.add.v4.f32 [%0], {%1, %2, %3, %4};"
                 :: "l"(p), "f"(v.x), "f"(v.y), "f"(v.z), "f"(v.w)
                 : "memory");
}

// agg[dst[e], off:off+64] += h[src[e], :]   (16 threads/edge, v4 reductions)
// ROWW = row width (in floats) of the destination table.
template<int ROWW, int OFF>
__global__ void scatter64_kernel(const float* __restrict__ h, const int* __restrict__ src,
                                 const int* __restrict__ dst, float* __restrict__ agg, int E) {
    long long idx = (long long)blockIdx.x * blockDim.x + threadIdx.x;
    int e = (int)(idx >> 4);
    if (e >= E) return;
    int g = (int)(idx & 15);
    int s = src[e], d = dst[e];
    float4 v = reinterpret_cast<const float4*>(h + (size_t)s * 64)[g];
    red_add_v4(agg + (size_t)d * ROWW + OFF + g * 4, v);
}

// Fused: read h1[src] ONCE per edge element; write
//   aggH1n[dst, g] += h1[src, g] * ns[src]     (layer-2 aggregate-then-transform)
//   aggJ  [dst, g] += h1[src, g]               (JK concat, first half)
__global__ void scatterH1_fused_kernel(const float* __restrict__ h1,
                                       const float* __restrict__ ns,
                                       const int* __restrict__ src,
                                       const int* __restrict__ dst,
                                       float* __restrict__ aggH1n,
                                       float* __restrict__ aggJ, int E) {
    long long idx = (long long)blockIdx.x * blockDim.x + threadIdx.x;
    int e = (int)(idx >> 4);
    if (e >= E) return;
    int g = (int)(idx & 15);
    int s = src[e], d = dst[e];
    float4 v = reinterpret_cast<const float4*>(h1 + (size_t)s * 64)[g];
    red_add_v4(aggJ + (size_t)d * 128 + g * 4, v);
    float sc = __ldg(&ns[s]);
    v.x *= sc; v.y *= sc; v.z *= sc; v.w *= sc;
    red_add_v4(aggH1n + (size_t)d * 64 + g * 4, v);
}

// h[node, col] = relu(agg[node, col] * nd[node] + b[col])
__global__ void post_kernel(const float* __restrict__ agg, const float* __restrict__ nd,
                            const float* __restrict__ b, float* __restrict__ h, int N) {
    int idx = blockIdx.x * blockDim.x + threadIdx.x;
    if (idx >= N * 16) return;
    int node = idx >> 4;
    int g    = idx & 15;
    float s  = nd[node];
    float4 v  = reinterpret_cast<const float4*>(agg)[idx];
    float4 bb = reinterpret_cast<const float4*>(b)[g];
    v.x = fmaxf(fmaf(v.x, s, bb.x), 0.f);
    v.y = fmaxf(fmaf(v.y, s, bb.y), 0.f);
    v.z = fmaxf(fmaf(v.z, s, bb.z), 0.f);
    v.w = fmaxf(fmaf(v.w, s, bb.w), 0.f);
    reinterpret_cast<float4*>(h)[idx] = v;
}

// ---------------- launch ----------------

extern "C" void kernel_launch(void* const* d_in, const int* in_sizes, int n_in,
                              void* d_out, int out_size) {
    const float* feats = (const float*)d_in[0];
    const int*   src   = (const int*)  d_in[1];
    const int*   dst   = (const int*)  d_in[2];
    const float* W1    = (const float*)d_in[3];
    const float* b1    = (const float*)d_in[4];
    const float* W2    = (const float*)d_in[5];
    const float* b2    = (const float*)d_in[6];
    const float* Wout  = (const float*)d_in[7];
    const float* bout  = (const float*)d_in[8];
    float* out = (float*)d_out;

    const int N = in_sizes[0] / 128;   // feats is [N, 128]
    const int E = in_sizes[1];

    float *p_ns, *p_nd, *p_pre, *p_agg1, *p_h1, *p_aggH1n, *p_agg2, *p_h2, *p_aggJ;
    cudaGetSymbolAddress((void**)&p_ns,     g_norm_s);
    cudaGetSymbolAddress((void**)&p_nd,     g_norm_d);
    cudaGetSymbolAddress((void**)&p_pre,    g_pre);
    cudaGetSymbolAddress((void**)&p_agg1,   g_agg1);
    cudaGetSymbolAddress((void**)&p_h1,     g_h1);
    cudaGetSymbolAddress((void**)&p_aggH1n, g_aggH1n);
    cudaGetSymbolAddress((void**)&p_agg2,   g_agg2);
    cudaGetSymbolAddress((void**)&p_h2,     g_h2);
    cudaGetSymbolAddress((void**)&p_aggJ,   g_aggJ);

    const int TB = 256;
    auto cdiv = [](long long a, long long b) { return (unsigned)((a + b - 1) / b); };

    // zero degree buffers + accumulators
    zero4_kernel<<<cdiv(N / 4,  TB), TB>>>(p_ns,     N / 4);
    zero4_kernel<<<cdiv(N / 4,  TB), TB>>>(p_nd,     N / 4);
    zero4_kernel<<<cdiv(N * 16, TB), TB>>>(p_agg1,   N * 16);
    zero4_kernel<<<cdiv(N * 16, TB), TB>>>(p_aggH1n, N * 16);
    zero4_kernel<<<cdiv(N * 32, TB), TB>>>(p_aggJ,   N * 32);

    // degrees -> norms
    degree_kernel<<<cdiv(E, TB), TB>>>(src, dst, p_ns, p_nd, E);
    norm_kernel  <<<cdiv(N, TB), TB>>>(p_ns, p_nd, N);

    const unsigned gemmGrid = (N + 3) / 4;

    // ---- layer 1: pre = (feats*ns)@W1 ; agg1 = segsum(pre[src]) ; h1 = relu(agg1*nd+b1)
    gemm64_kernel<128, true, false><<<gemmGrid, TB>>>(feats, W1, p_ns, nullptr, p_pre, N);
    scatter64_kernel<64, 0><<<cdiv((long long)E * 16, TB), TB>>>(p_pre, src, dst, p_agg1, E);
    post_kernel<<<cdiv(N * 16, TB), TB>>>(p_agg1, p_nd, b1, p_h1, N);

    // ---- fused: aggH1n = segsum(h1*ns [src]);  aggJ[:, 0:64] = segsum(h1[src])
    scatterH1_fused_kernel<<<cdiv((long long)E * 16, TB), TB>>>(p_h1, p_ns, src, dst,
                                                                p_aggH1n, p_aggJ, E);

    // ---- layer 2 (aggregate-then-transform): agg2 = aggH1n @ W2 ; h2 = relu(agg2*nd+b2)
    gemm64_kernel<64, false, false><<<gemmGrid, TB>>>(p_aggH1n, W2, nullptr, nullptr, p_agg2, N);
    post_kernel<<<cdiv(N * 16, TB), TB>>>(p_agg2, p_nd, b2, p_h2, N);

    // ---- JK second half: aggJ[:, 64:128] += h2[src]
    scatter64_kernel<128, 64><<<cdiv((long long)E * 16, TB), TB>>>(p_h2, src, dst, p_aggJ, E);

    // ---- out = aggJ @ Wout + bout
    gemm64_kernel<128, false, true><<<gemmGrid, TB>>>(p_aggJ, Wout, nullptr, bout, out, N);
}

// round 4
// speedup vs baseline: 1.9506x; 1.9506x over previous
#include <cuda_runtime.h>
#include <cstdint>

#define NMAX 100000
#define EMAX 1600000

// ---------------- scratch (static device globals; no allocation) ----------------
__device__ int   g_degin [NMAX];
__device__ int   g_degout[NMAX];
__device__ float g_ns[NMAX];
__device__ float g_nd[NMAX];
__device__ int   g_rowptr[NMAX + 1];
__device__ int   g_cursor[NMAX];
__device__ int   g_bsum[256];            // >= ceil(NMAX/512) = 196
__device__ int   g_colidx[EMAX];
__device__ float g_pre [NMAX * 64];
__device__ float g_h1  [NMAX * 64];
__device__ float g_h1n [NMAX * 64];      // h1 * norm_s  (layer-2 payload)
__device__ float g_agg [NMAX * 64];      // segsum(h1n[src])
__device__ float g_h2  [NMAX * 64];
__device__ float g_y   [NMAX * 64];      // [h1|h2] @ Wout per node

// ---------------- small kernels ----------------

__global__ void zero_deg_kernel(int* __restrict__ a, int* __restrict__ b, int N) {
    int i = blockIdx.x * blockDim.x + threadIdx.x;
    if (i < N) { a[i] = 0; b[i] = 0; }
}

__global__ void degree_kernel(const int* __restrict__ src, const int* __restrict__ dst,
                              int* __restrict__ dout, int* __restrict__ din, int E) {
    int e = blockIdx.x * blockDim.x + threadIdx.x;
    if (e >= E) return;
    atomicAdd(&dout[src[e]], 1);
    atomicAdd(&din [dst[e]], 1);
}

__global__ void norm_kernel(const int* __restrict__ dout, const int* __restrict__ din,
                            float* __restrict__ ns, float* __restrict__ nd, int N) {
    int i = blockIdx.x * blockDim.x + threadIdx.x;
    if (i >= N) return;
    ns[i] = rsqrtf((float)max(dout[i], 1));
    nd[i] = rsqrtf((float)max(din [i], 1));
}

// exclusive scan of deg_in -> rowptr (3-kernel two-level scan)
__global__ void scan1_kernel(const int* __restrict__ deg, int* __restrict__ rowptr,
                             int* __restrict__ bsum, int N) {
    __shared__ int s[512];
    int t = threadIdx.x;
    int i = blockIdx.x * 512 + t;
    int v = (i < N) ? deg[i] : 0;
    s[t] = v; __syncthreads();
    for (int off = 1; off < 512; off <<= 1) {
        int u = (t >= off) ? s[t - off] : 0;
        __syncthreads();
        s[t] += u;
        __syncthreads();
    }
    if (i < N) rowptr[i] = s[t] - v;        // exclusive
    if (t == 511) bsum[blockIdx.x] = s[511];
}

__global__ void scan2_kernel(int* __restrict__ bsum, int nb) {
    __shared__ int s[256];
    int t = threadIdx.x;
    int v = (t < nb) ? bsum[t] : 0;
    s[t] = v; __syncthreads();
    for (int off = 1; off < 256; off <<= 1) {
        int u = (t >= off) ? s[t - off] : 0;
        __syncthreads();
        s[t] += u;
        __syncthreads();
    }
    if (t < nb) bsum[t] = s[t] - v;         // exclusive
}

__global__ void scan3_kernel(int* __restrict__ rowptr, int* __restrict__ cursor,
                             const int* __restrict__ bsum, int N, int E) {
    int i = blockIdx.x * blockDim.x + threadIdx.x;
    if (i < N) {
        int r = rowptr[i] + bsum[i >> 9];
        rowptr[i] = r;
        cursor[i] = r;
    }
    if (i == 0) rowptr[N] = E;
}

__global__ void csrfill_kernel(const int* __restrict__ src, const int* __restrict__ dst,
                               int* __restrict__ cursor, int* __restrict__ colidx, int E) {
    int e = blockIdx.x * blockDim.x + threadIdx.x;
    if (e >= E) return;
    int slot = atomicAdd(&cursor[dst[e]], 1);
    colidx[slot] = src[e];
}

// ---------------- GEMM: out[N,64] = A[N,K] (opt *ns) @ W[K,64], 32 nodes/block ----------------
// EPI: 0 = plain store, 1 = relu(val*nd[node] + bias[col])
template<int K, bool SCALE, bool CONCAT, int EPI>
__global__ void __launch_bounds__(256)
gemm64_kernel(const float* __restrict__ A, const float* __restrict__ A2,
              const float* __restrict__ W,
              const float* __restrict__ ns, const float* __restrict__ nd,
              const float* __restrict__ bias,
              float* __restrict__ out, int N) {
    __shared__ float sW[K * 64];
    __shared__ float sA[32 * K];
    const int tid = threadIdx.x;
    constexpr int K4 = K / 4;

    for (int i = tid; i < K * 16; i += 256)
        reinterpret_cast<float4*>(sW)[i] = reinterpret_cast<const float4*>(W)[i];

    const int n0 = blockIdx.x * 32;
    for (int i = tid; i < 32 * K4; i += 256) {
        int r = i / K4, f = i % K4;
        int node = n0 + r;
        float4 v = make_float4(0.f, 0.f, 0.f, 0.f);
        if (node < N) {
            if (CONCAT) {
                if (f < 16) v = reinterpret_cast<const float4*>(A  + (size_t)node * 64)[f];
                else        v = reinterpret_cast<const float4*>(A2 + (size_t)node * 64)[f - 16];
            } else {
                v = reinterpret_cast<const float4*>(A + (size_t)node * K)[f];
            }
            if (SCALE) {
                float s = ns[node];
                v.x *= s; v.y *= s; v.z *= s; v.w *= s;
            }
        }
        reinterpret_cast<float4*>(sA)[i] = v;
    }
    __syncthreads();

    const int col = tid & 63, rgrp = tid >> 6;
    float acc[8];
#pragma unroll
    for (int j = 0; j < 8; j++) acc[j] = 0.f;

    for (int k4 = 0; k4 < K4; k4++) {
        float4 a[8];
#pragma unroll
        for (int j = 0; j < 8; j++)
            a[j] = reinterpret_cast<float4*>(sA)[(rgrp + 4 * j) * K4 + k4];
#pragma unroll
        for (int kk = 0; kk < 4; kk++) {
            float w = sW[(k4 * 4 + kk) * 64 + col];
#pragma unroll
            for (int j = 0; j < 8; j++) {
                float av = (kk == 0) ? a[j].x : (kk == 1) ? a[j].y : (kk == 2) ? a[j].z : a[j].w;
                acc[j] = fmaf(av, w, acc[j]);
            }
        }
    }

#pragma unroll
    for (int j = 0; j < 8; j++) {
        int node = n0 + rgrp + 4 * j;
        if (node < N) {
            float v = acc[j];
            if (EPI == 1) v = fmaxf(fmaf(v, nd[node], bias[col]), 0.f);
            out[(size_t)node * 64 + col] = v;
        }
    }
}

// ---------------- pull aggregation: one warp per destination node ----------------
// EPI: 0 = plain store to o1
//      1 = h = relu(acc*nd + b); o1 = h; o2 = h * ns   (layer-1 epilogue)
//      2 = o1 = acc + b                                 (output epilogue)
template<int EPI>
__global__ void __launch_bounds__(256)
pull64_kernel(const float* __restrict__ tab,
              const int* __restrict__ rowptr, const int* __restrict__ colidx,
              const float* __restrict__ ns, const float* __restrict__ nd,
              const float* __restrict__ b,
              float* __restrict__ o1, float* __restrict__ o2, int N) {
    int node = (blockIdx.x * blockDim.x + threadIdx.x) >> 5;
    if (node >= N) return;
    int lane = threadIdx.x & 31;
    int beg = __ldg(&rowptr[node]);
    int end = __ldg(&rowptr[node + 1]);
    int deg = end - beg;

    float2 acc = make_float2(0.f, 0.f);

    if (deg > 0) {
        // software-pipelined gather: load next row while accumulating current
        int my = __ldg(&colidx[beg + ((lane < deg) ? lane : 0)]);
        int chunk = (deg < 32) ? deg : 32;
        int s0 = __shfl_sync(0xffffffffu, my, 0);
        float2 cur = reinterpret_cast<const float2*>(tab + (size_t)s0 * 64)[lane];
        int jg = 1;                 // global index of next edge to load (within row)
        int jl = 1;                 // lane-index within current chunk
        int loaded = chunk;         // edges consumed from colidx so far (for refill)
        while (true) {
            float2 nxt;
            bool have_next = (jg < deg);
            if (have_next) {
                if (jl == chunk) {  // refill index register
                    int rem = deg - loaded;
                    my = __ldg(&colidx[beg + loaded + ((lane < rem) ? lane : 0)]);
                    chunk = (rem < 32) ? rem : 32;
                    loaded += chunk;
                    jl = 0;
                }
                int s = __shfl_sync(0xffffffffu, my, jl);
                nxt = reinterpret_cast<const float2*>(tab + (size_t)s * 64)[lane];
                jl++;
            }
            acc.x += cur.x; acc.y += cur.y;
            if (!have_next) break;
            cur = nxt;
            jg++;
        }
    }

    if (EPI == 0) {
        reinterpret_cast<float2*>(o1 + (size_t)node * 64)[lane] = acc;
    } else if (EPI == 1) {
        float d = nd[node];
        float2 bb = reinterpret_cast<const float2*>(b)[lane];
        float2 h;
        h.x = fmaxf(fmaf(acc.x, d, bb.x), 0.f);
        h.y = fmaxf(fmaf(acc.y, d, bb.y), 0.f);
        reinterpret_cast<float2*>(o1 + (size_t)node * 64)[lane] = h;
        float sn = ns[node];
        float2 hn = make_float2(h.x * sn, h.y * sn);
        reinterpret_cast<float2*>(o2 + (size_t)node * 64)[lane] = hn;
    } else {
        float2 bb = reinterpret_cast<const float2*>(b)[lane];
        acc.x += bb.x; acc.y += bb.y;
        reinterpret_cast<float2*>(o1 + (size_t)node * 64)[lane] = acc;
    }
}

// ---------------- launch ----------------

extern "C" void kernel_launch(void* const* d_in, const int* in_sizes, int n_in,
                              void* d_out, int out_size) {
    const float* feats = (const float*)d_in[0];
    const int*   src   = (const int*)  d_in[1];
    const int*   dst   = (const int*)  d_in[2];
    const float* W1    = (const float*)d_in[3];
    const float* b1    = (const float*)d_in[4];
    const float* W2    = (const float*)d_in[5];
    const float* b2    = (const float*)d_in[6];
    const float* Wout  = (const float*)d_in[7];
    const float* bout  = (const float*)d_in[8];
    float* out = (float*)d_out;

    const int N = in_sizes[0] / 128;
    const int E = in_sizes[1];

    int *p_degin, *p_degout, *p_rowptr, *p_cursor, *p_bsum, *p_colidx;
    float *p_ns, *p_nd, *p_pre, *p_h1, *p_h1n, *p_agg, *p_h2, *p_y;
    cudaGetSymbolAddress((void**)&p_degin,  g_degin);
    cudaGetSymbolAddress((void**)&p_degout, g_degout);
    cudaGetSymbolAddress((void**)&p_rowptr, g_rowptr);
    cudaGetSymbolAddress((void**)&p_cursor, g_cursor);
    cudaGetSymbolAddress((void**)&p_bsum,   g_bsum);
    cudaGetSymbolAddress((void**)&p_colidx, g_colidx);
    cudaGetSymbolAddress((void**)&p_ns,     g_ns);
    cudaGetSymbolAddress((void**)&p_nd,     g_nd);
    cudaGetSymbolAddress((void**)&p_pre,    g_pre);
    cudaGetSymbolAddress((void**)&p_h1,     g_h1);
    cudaGetSymbolAddress((void**)&p_h1n,    g_h1n);
    cudaGetSymbolAddress((void**)&p_agg,    g_agg);
    cudaGetSymbolAddress((void**)&p_h2,     g_h2);
    cudaGetSymbolAddress((void**)&p_y,      g_y);

    const int TB = 256;
    auto cdiv = [](long long a, long long b) { return (unsigned)((a + b - 1) / b); };
    const int nb = (int)cdiv(N, 512);       // scan blocks (196 for N=100k; must be <= 256)

    // ---- degrees + norms
    zero_deg_kernel<<<cdiv(N, TB), TB>>>(p_degin, p_degout, N);
    degree_kernel  <<<cdiv(E, TB), TB>>>(src, dst, p_degout, p_degin, E);
    norm_kernel    <<<cdiv(N, TB), TB>>>(p_degout, p_degin, p_ns, p_nd, N);

    // ---- CSR by destination (atomic-free aggregation afterwards)
    scan1_kernel<<<nb, 512>>>(p_degin, p_rowptr, p_bsum, N);
    scan2_kernel<<<1, 256>>>(p_bsum, nb);
    scan3_kernel<<<cdiv(N, TB), TB>>>(p_rowptr, p_cursor, p_bsum, N, E);
    csrfill_kernel<<<cdiv(E, TB), TB>>>(src, dst, p_cursor, p_colidx, E);

    const unsigned gemmGrid = cdiv(N, 32);
    const unsigned pullGrid = cdiv((long long)N * 32, TB);

    // ---- layer 1: pre = (feats*ns)@W1; h1 = relu(pull(pre)*nd + b1); h1n = h1*ns
    gemm64_kernel<128, true, false, 0><<<gemmGrid, TB>>>(feats, nullptr, W1, p_ns, nullptr, nullptr, p_pre, N);
    pull64_kernel<1><<<pullGrid, TB>>>(p_pre, p_rowptr, p_colidx, p_ns, p_nd, b1, p_h1, p_h1n, N);

    // ---- layer 2 (aggregate-then-transform): agg = pull(h1n); h2 = relu((agg@W2)*nd + b2)
    pull64_kernel<0><<<pullGrid, TB>>>(p_h1n, p_rowptr, p_colidx, nullptr, nullptr, nullptr, p_agg, nullptr, N);
    gemm64_kernel<64, false, false, 1><<<gemmGrid, TB>>>(p_agg, nullptr, W2, nullptr, p_nd, b2, p_h2, N);

    // ---- output: y = [h1|h2]@Wout; out = pull(y) + bout
    gemm64_kernel<128, false, true, 0><<<gemmGrid, TB>>>(p_h1, p_h2, Wout, nullptr, nullptr, nullptr, p_y, N);
    pull64_kernel<2><<<pullGrid, TB>>>(p_y, p_rowptr, p_colidx, nullptr, nullptr, bout, out, nullptr, N);
}

// round 5
// speedup vs baseline: 2.3958x; 1.2283x over previous
#include <cuda_runtime.h>
#include <cstdint>

#define NMAX 100000
#define EMAX 1600000

// ---------------- scratch (static device globals; no allocation) ----------------
__device__ int   g_degin [NMAX];
__device__ int   g_degout[NMAX];
__device__ float g_ns[NMAX];
__device__ float g_nd[NMAX];
__device__ int   g_rowptr[NMAX + 1];
__device__ int   g_cursor[NMAX];
__device__ int   g_bsum[256];            // >= ceil(NMAX/512) = 196
__device__ int   g_colidx[EMAX];
__device__ __align__(256) float g_pre [NMAX * 64];
__device__ __align__(256) float g_h1  [NMAX * 64];
__device__ __align__(256) float g_h1n [NMAX * 64];   // h1 * norm_s (layer-2 payload)
__device__ __align__(256) float g_agg [NMAX * 64];   // segsum(h1n[src])
__device__ __align__(256) float g_h2  [NMAX * 64];
__device__ __align__(256) float g_y   [NMAX * 64];   // [h1|h2] @ Wout per node

// ---------------- small kernels ----------------

__global__ void zero_deg_kernel(int* __restrict__ a, int* __restrict__ b, int N) {
    int i = blockIdx.x * blockDim.x + threadIdx.x;
    if (i < N) { a[i] = 0; b[i] = 0; }
}

__global__ void degree_kernel(const int* __restrict__ src, const int* __restrict__ dst,
                              int* __restrict__ dout, int* __restrict__ din, int E) {
    int e = blockIdx.x * blockDim.x + threadIdx.x;
    if (e >= E) return;
    atomicAdd(&dout[src[e]], 1);
    atomicAdd(&din [dst[e]], 1);
}

__global__ void norm_kernel(const int* __restrict__ dout, const int* __restrict__ din,
                            float* __restrict__ ns, float* __restrict__ nd, int N) {
    int i = blockIdx.x * blockDim.x + threadIdx.x;
    if (i >= N) return;
    ns[i] = rsqrtf((float)max(dout[i], 1));
    nd[i] = rsqrtf((float)max(din [i], 1));
}

// exclusive scan of deg_in -> rowptr (3-kernel two-level scan)
__global__ void scan1_kernel(const int* __restrict__ deg, int* __restrict__ rowptr,
                             int* __restrict__ bsum, int N) {
    __shared__ int s[512];
    int t = threadIdx.x;
    int i = blockIdx.x * 512 + t;
    int v = (i < N) ? deg[i] : 0;
    s[t] = v; __syncthreads();
    for (int off = 1; off < 512; off <<= 1) {
        int u = (t >= off) ? s[t - off] : 0;
        __syncthreads();
        s[t] += u;
        __syncthreads();
    }
    if (i < N) rowptr[i] = s[t] - v;        // exclusive
    if (t == 511) bsum[blockIdx.x] = s[511];
}

__global__ void scan2_kernel(int* __restrict__ bsum, int nb) {
    __shared__ int s[256];
    int t = threadIdx.x;
    int v = (t < nb) ? bsum[t] : 0;
    s[t] = v; __syncthreads();
    for (int off = 1; off < 256; off <<= 1) {
        int u = (t >= off) ? s[t - off] : 0;
        __syncthreads();
        s[t] += u;
        __syncthreads();
    }
    if (t < nb) bsum[t] = s[t] - v;         // exclusive
}

__global__ void scan3_kernel(int* __restrict__ rowptr, int* __restrict__ cursor,
                             const int* __restrict__ bsum, int N, int E) {
    int i = blockIdx.x * blockDim.x + threadIdx.x;
    if (i < N) {
        int r = rowptr[i] + bsum[i >> 9];
        rowptr[i] = r;
        cursor[i] = r;
    }
    if (i == 0) rowptr[N] = E;
}

__global__ void csrfill_kernel(const int* __restrict__ src, const int* __restrict__ dst,
                               int* __restrict__ cursor, int* __restrict__ colidx, int E) {
    int e = blockIdx.x * blockDim.x + threadIdx.x;
    if (e >= E) return;
    int slot = atomicAdd(&cursor[dst[e]], 1);
    colidx[slot] = src[e];
}

// ---------------- GEMM: out[N,64] = A[N,K] (opt *ns) @ W[K,64], 32 nodes/block ----------------
// EPI: 0 = plain store, 1 = relu(val*nd[node] + bias[col])
template<int K, bool SCALE, bool CONCAT, int EPI>
__global__ void __launch_bounds__(256)
gemm64_kernel(const float* __restrict__ A, const float* __restrict__ A2,
              const float* __restrict__ W,
              const float* __restrict__ ns, const float* __restrict__ nd,
              const float* __restrict__ bias,
              float* __restrict__ out, int N) {
    __shared__ float sW[K * 64];
    __shared__ float sA[32 * K];
    const int tid = threadIdx.x;
    constexpr int K4 = K / 4;

    for (int i = tid; i < K * 16; i += 256)
        reinterpret_cast<float4*>(sW)[i] = reinterpret_cast<const float4*>(W)[i];

    const int n0 = blockIdx.x * 32;
    for (int i = tid; i < 32 * K4; i += 256) {
        int r = i / K4, f = i % K4;
        int node = n0 + r;
        float4 v = make_float4(0.f, 0.f, 0.f, 0.f);
        if (node < N) {
            if (CONCAT) {
                if (f < 16) v = reinterpret_cast<const float4*>(A  + (size_t)node * 64)[f];
                else        v = reinterpret_cast<const float4*>(A2 + (size_t)node * 64)[f - 16];
            } else {
                v = reinterpret_cast<const float4*>(A + (size_t)node * K)[f];
            }
            if (SCALE) {
                float s = ns[node];
                v.x *= s; v.y *= s; v.z *= s; v.w *= s;
            }
        }
        reinterpret_cast<float4*>(sA)[i] = v;
    }
    __syncthreads();

    const int col = tid & 63, rgrp = tid >> 6;
    float acc[8];
#pragma unroll
    for (int j = 0; j < 8; j++) acc[j] = 0.f;

    for (int k4 = 0; k4 < K4; k4++) {
        float4 a[8];
#pragma unroll
        for (int j = 0; j < 8; j++)
            a[j] = reinterpret_cast<float4*>(sA)[(rgrp + 4 * j) * K4 + k4];
#pragma unroll
        for (int kk = 0; kk < 4; kk++) {
            float w = sW[(k4 * 4 + kk) * 64 + col];
#pragma unroll
            for (int j = 0; j < 8; j++) {
                float av = (kk == 0) ? a[j].x : (kk == 1) ? a[j].y : (kk == 2) ? a[j].z : a[j].w;
                acc[j] = fmaf(av, w, acc[j]);
            }
        }
    }

#pragma unroll
    for (int j = 0; j < 8; j++) {
        int node = n0 + rgrp + 4 * j;
        if (node < N) {
            float v = acc[j];
            if (EPI == 1) v = fmaxf(fmaf(v, nd[node], bias[col]), 0.f);
            out[(size_t)node * 64 + col] = v;
        }
    }
}

// ---------------- pull aggregation: one warp per destination node ----------------
// Half-warp float4 layout: lane = half*16 + q. One warp LDG.128 fetches TWO edge
// rows at once (half 0 -> even edge, half 1 -> odd edge). Cross-half combine at end.
// EPI: 0 = plain store; 1 = h=relu(acc*nd+b), o1=h, o2=h*ns; 2 = o1 = acc + b
template<int EPI>
__global__ void __launch_bounds__(256)
pull64_kernel(const float* __restrict__ tab,
              const int* __restrict__ rowptr, const int* __restrict__ colidx,
              const float* __restrict__ ns, const float* __restrict__ nd,
              const float* __restrict__ b,
              float* __restrict__ o1, float* __restrict__ o2, int N) {
    int node = (blockIdx.x * blockDim.x + threadIdx.x) >> 5;
    if (node >= N) return;
    const int lane = threadIdx.x & 31;
    const int half = lane >> 4;       // which edge of the pair this lane serves
    const int q    = lane & 15;       // float4 slot within the 64-float row
    const int beg = __ldg(&rowptr[node]);
    const int deg = __ldg(&rowptr[node + 1]) - beg;

    float4 acc = make_float4(0.f, 0.f, 0.f, 0.f);

    int i = 0;
    while (i < deg) {
        int rem   = deg - i;
        int chunk = (rem < 32) ? rem : 32;
        int my = __ldg(&colidx[beg + i + ((lane < chunk) ? lane : 0)]);
        int npairs = (chunk + 1) >> 1;
#pragma unroll 4
        for (int p = 0; p < npairs; p++) {
            int j = 2 * p + half;
            bool act = (j < chunk);
            int s = __shfl_sync(0xffffffffu, my, act ? j : 0);
            float4 v = reinterpret_cast<const float4*>(tab + (size_t)s * 64)[q];
            if (act) { acc.x += v.x; acc.y += v.y; acc.z += v.z; acc.w += v.w; }
        }
        i += chunk;
    }

    // combine the two halves (lanes q and q+16 hold the same columns)
    acc.x += __shfl_xor_sync(0xffffffffu, acc.x, 16);
    acc.y += __shfl_xor_sync(0xffffffffu, acc.y, 16);
    acc.z += __shfl_xor_sync(0xffffffffu, acc.z, 16);
    acc.w += __shfl_xor_sync(0xffffffffu, acc.w, 16);

    if (half != 0) return;

    if (EPI == 0) {
        reinterpret_cast<float4*>(o1 + (size_t)node * 64)[q] = acc;
    } else if (EPI == 1) {
        float d = nd[node];
        float4 bb = reinterpret_cast<const float4*>(b)[q];
        float4 h;
        h.x = fmaxf(fmaf(acc.x, d, bb.x), 0.f);
        h.y = fmaxf(fmaf(acc.y, d, bb.y), 0.f);
        h.z = fmaxf(fmaf(acc.z, d, bb.z), 0.f);
        h.w = fmaxf(fmaf(acc.w, d, bb.w), 0.f);
        reinterpret_cast<float4*>(o1 + (size_t)node * 64)[q] = h;
        float sn = ns[node];
        float4 hn = make_float4(h.x * sn, h.y * sn, h.z * sn, h.w * sn);
        reinterpret_cast<float4*>(o2 + (size_t)node * 64)[q] = hn;
    } else {
        float4 bb = reinterpret_cast<const float4*>(b)[q];
        acc.x += bb.x; acc.y += bb.y; acc.z += bb.z; acc.w += bb.w;
        reinterpret_cast<float4*>(o1 + (size_t)node * 64)[q] = acc;
    }
}

// ---------------- launch ----------------

extern "C" void kernel_launch(void* const* d_in, const int* in_sizes, int n_in,
                              void* d_out, int out_size) {
    const float* feats = (const float*)d_in[0];
    const int*   src   = (const int*)  d_in[1];
    const int*   dst   = (const int*)  d_in[2];
    const float* W1    = (const float*)d_in[3];
    const float* b1    = (const float*)d_in[4];
    const float* W2    = (const float*)d_in[5];
    const float* b2    = (const float*)d_in[6];
    const float* Wout  = (const float*)d_in[7];
    const float* bout  = (const float*)d_in[8];
    float* out = (float*)d_out;

    const int N = in_sizes[0] / 128;
    const int E = in_sizes[1];

    int *p_degin, *p_degout, *p_rowptr, *p_cursor, *p_bsum, *p_colidx;
    float *p_ns, *p_nd, *p_pre, *p_h1, *p_h1n, *p_agg, *p_h2, *p_y;
    cudaGetSymbolAddress((void**)&p_degin,  g_degin);
    cudaGetSymbolAddress((void**)&p_degout, g_degout);
    cudaGetSymbolAddress((void**)&p_rowptr, g_rowptr);
    cudaGetSymbolAddress((void**)&p_cursor, g_cursor);
    cudaGetSymbolAddress((void**)&p_bsum,   g_bsum);
    cudaGetSymbolAddress((void**)&p_colidx, g_colidx);
    cudaGetSymbolAddress((void**)&p_ns,     g_ns);
    cudaGetSymbolAddress((void**)&p_nd,     g_nd);
    cudaGetSymbolAddress((void**)&p_pre,    g_pre);
    cudaGetSymbolAddress((void**)&p_h1,     g_h1);
    cudaGetSymbolAddress((void**)&p_h1n,    g_h1n);
    cudaGetSymbolAddress((void**)&p_agg,    g_agg);
    cudaGetSymbolAddress((void**)&p_h2,     g_h2);
    cudaGetSymbolAddress((void**)&p_y,      g_y);

    const int TB = 256;
    auto cdiv = [](long long a, long long b) { return (unsigned)((a + b - 1) / b); };
    const int nb = (int)cdiv(N, 512);       // scan blocks (196 for N=100k; <= 256)

    // ---- degrees + norms
    zero_deg_kernel<<<cdiv(N, TB), TB>>>(p_degin, p_degout, N);
    degree_kernel  <<<cdiv(E, TB), TB>>>(src, dst, p_degout, p_degin, E);
    norm_kernel    <<<cdiv(N, TB), TB>>>(p_degout, p_degin, p_ns, p_nd, N);

    // ---- CSR by destination (atomic-free aggregation afterwards)
    scan1_kernel<<<nb, 512>>>(p_degin, p_rowptr, p_bsum, N);
    scan2_kernel<<<1, 256>>>(p_bsum, nb);
    scan3_kernel<<<cdiv(N, TB), TB>>>(p_rowptr, p_cursor, p_bsum, N, E);
    csrfill_kernel<<<cdiv(E, TB), TB>>>(src, dst, p_cursor, p_colidx, E);

    const unsigned gemmGrid = cdiv(N, 32);
    const unsigned pullGrid = cdiv((long long)N * 32, TB);

    // ---- layer 1: pre = (feats*ns)@W1; h1 = relu(pull(pre)*nd + b1); h1n = h1*ns
    gemm64_kernel<128, true, false, 0><<<gemmGrid, TB>>>(feats, nullptr, W1, p_ns, nullptr, nullptr, p_pre, N);
    pull64_kernel<1><<<pullGrid, TB>>>(p_pre, p_rowptr, p_colidx, p_ns, p_nd, b1, p_h1, p_h1n, N);

    // ---- layer 2 (aggregate-then-transform): agg = pull(h1n); h2 = relu((agg@W2)*nd + b2)
    pull64_kernel<0><<<pullGrid, TB>>>(p_h1n, p_rowptr, p_colidx, nullptr, nullptr, nullptr, p_agg, nullptr, N);
    gemm64_kernel<64, false, false, 1><<<gemmGrid, TB>>>(p_agg, nullptr, W2, nullptr, p_nd, b2, p_h2, N);

    // ---- output: y = [h1|h2]@Wout; out = pull(y) + bout
    gemm64_kernel<128, false, true, 0><<<gemmGrid, TB>>>(p_h1, p_h2, Wout, nullptr, nullptr, nullptr, p_y, N);
    pull64_kernel<2><<<pullGrid, TB>>>(p_y, p_rowptr, p_colidx, nullptr, nullptr, bout, out, nullptr, N);
}

// round 7
// speedup vs baseline: 2.8789x; 1.2016x over previous
#include <cuda_runtime.h>
#include <cuda_bf16.h>
#include <cstdint>

#define NMAX 100000
#define EMAX 1600000

// ---------------- scratch (static device globals; no allocation) ----------------
__device__ int   g_degin [NMAX];
__device__ int   g_degout[NMAX];
__device__ float g_ns[NMAX];
__device__ float g_nd[NMAX];
__device__ int   g_rowptr[NMAX + 1];
__device__ int   g_cursor[NMAX];
__device__ int   g_bsum[256];
__device__ int   g_colidx[EMAX];
__device__ __align__(256) float g_pre [NMAX * 64];
__device__ __align__(256) float g_h1  [NMAX * 64];
__device__ __align__(256) float g_h1n [NMAX * 64];
__device__ __align__(256) float g_agg [NMAX * 64];
__device__ __align__(256) float g_h2  [NMAX * 64];
__device__ __align__(256) float g_y   [NMAX * 64];

// ---------------- small kernels ----------------

__global__ void zero_deg_kernel(int* __restrict__ a, int* __restrict__ b, int N) {
    int i = blockIdx.x * blockDim.x + threadIdx.x;
    if (i < N) { a[i] = 0; b[i] = 0; }
}

__global__ void degree_kernel(const int* __restrict__ src, const int* __restrict__ dst,
                              int* __restrict__ dout, int* __restrict__ din, int E) {
    int e = blockIdx.x * blockDim.x + threadIdx.x;
    if (e >= E) return;
    atomicAdd(&dout[src[e]], 1);
    atomicAdd(&din [dst[e]], 1);
}

__global__ void norm_kernel(const int* __restrict__ dout, const int* __restrict__ din,
                            float* __restrict__ ns, float* __restrict__ nd, int N) {
    int i = blockIdx.x * blockDim.x + threadIdx.x;
    if (i >= N) return;
    ns[i] = rsqrtf((float)max(dout[i], 1));
    nd[i] = rsqrtf((float)max(din [i], 1));
}

__global__ void scan1_kernel(const int* __restrict__ deg, int* __restrict__ rowptr,
                             int* __restrict__ bsum, int N) {
    __shared__ int s[512];
    int t = threadIdx.x;
    int i = blockIdx.x * 512 + t;
    int v = (i < N) ? deg[i] : 0;
    s[t] = v; __syncthreads();
    for (int off = 1; off < 512; off <<= 1) {
        int u = (t >= off) ? s[t - off] : 0;
        __syncthreads();
        s[t] += u;
        __syncthreads();
    }
    if (i < N) rowptr[i] = s[t] - v;
    if (t == 511) bsum[blockIdx.x] = s[511];
}

__global__ void scan2_kernel(int* __restrict__ bsum, int nb) {
    __shared__ int s[256];
    int t = threadIdx.x;
    int v = (t < nb) ? bsum[t] : 0;
    s[t] = v; __syncthreads();
    for (int off = 1; off < 256; off <<= 1) {
        int u = (t >= off) ? s[t - off] : 0;
        __syncthreads();
        s[t] += u;
        __syncthreads();
    }
    if (t < nb) bsum[t] = s[t] - v;
}

__global__ void scan3_kernel(int* __restrict__ rowptr, int* __restrict__ cursor,
                             const int* __restrict__ bsum, int N, int E) {
    int i = blockIdx.x * blockDim.x + threadIdx.x;
    if (i < N) {
        int r = rowptr[i] + bsum[i >> 9];
        rowptr[i] = r;
        cursor[i] = r;
    }
    if (i == 0) rowptr[N] = E;
}

__global__ void csrfill_kernel(const int* __restrict__ src, const int* __restrict__ dst,
                               int* __restrict__ cursor, int* __restrict__ colidx, int E) {
    int e = blockIdx.x * blockDim.x + threadIdx.x;
    if (e >= E) return;
    int slot = atomicAdd(&cursor[dst[e]], 1);
    colidx[slot] = src[e];
}

// ================= split-bf16 mma.sync GEMM (compute_100-legal) =================

__device__ __forceinline__ void mma_bf16(float* c, const uint32_t* a, const uint32_t* b) {
    asm volatile(
        "mma.sync.aligned.m16n8k16.row.col.f32.bf16.bf16.f32 "
        "{%0,%1,%2,%3}, {%4,%5,%6,%7}, {%8,%9}, {%0,%1,%2,%3};"
        : "+f"(c[0]), "+f"(c[1]), "+f"(c[2]), "+f"(c[3])
        : "r"(a[0]), "r"(a[1]), "r"(a[2]), "r"(a[3]), "r"(b[0]), "r"(b[1]));
}

// pack two floats into (hi bf16x2, lo bf16x2)
__device__ __forceinline__ void cvt_pair(float f0, float f1, uint32_t& hi, uint32_t& lo) {
    __nv_bfloat16 h0 = __float2bfloat16(f0);
    __nv_bfloat16 h1 = __float2bfloat16(f1);
    __nv_bfloat16 l0 = __float2bfloat16(f0 - __bfloat162float(h0));
    __nv_bfloat16 l1 = __float2bfloat16(f1 - __bfloat162float(h1));
    hi = (uint32_t)__bfloat16_as_ushort(h0) | ((uint32_t)__bfloat16_as_ushort(h1) << 16);
    lo = (uint32_t)__bfloat16_as_ushort(l0) | ((uint32_t)__bfloat16_as_ushort(l1) << 16);
}

// out[N,64] = A[N,K](*ns opt / concat opt) @ W[K,64].
// Block: 256 thr = 8 warps; tile 128 rows. Warp w -> rows 16w..16w+15, all 64 cols.
// Smem (uint32 units, pitch P = K/2+4): A_hi[128][P], A_lo[128][P], B_hi[64][P], B_lo[64][P],
// where each uint32 packs 2 consecutive-k bf16. B[n][k] = W[k][n].
// EPI: 0 plain store; 1 relu(v*nd[row] + bias[col]).
template<int K, bool SCALE, bool CONCAT, int EPI>
__global__ void __launch_bounds__(256)
mma_gemm_kernel(const float* __restrict__ A, const float* __restrict__ A2,
                const float* __restrict__ W,
                const float* __restrict__ ns, const float* __restrict__ nd,
                const float* __restrict__ bias,
                float* __restrict__ out, int N) {
    extern __shared__ uint32_t sm[];
    constexpr int P   = K / 2 + 4;          // pitch in uint32 (bank-conflict-free: P%32==4 or 36%32=4)
    constexpr int K4  = K / 4;              // float4s per A row
    uint32_t* sAh = sm;
    uint32_t* sAl = sm + 128 * P;
    uint32_t* sBh = sm + 256 * P;
    uint32_t* sBl = sm + 256 * P + 64 * P;

    const int tid = threadIdx.x;
    const int wid = tid >> 5, lane = tid & 31;
    const int gid = lane >> 2, t = lane & 3;
    const int n0 = blockIdx.x * 128;

    // ---- stage A (hi/lo packed pairs)
    for (int idx = tid; idx < 128 * K4; idx += 256) {
        int m = idx / K4, f = idx % K4;     // float4 index along k
        int node = n0 + m;
        float4 v = make_float4(0.f, 0.f, 0.f, 0.f);
        if (node < N) {
            if (CONCAT) v = (f < 16) ? reinterpret_cast<const float4*>(A  + (size_t)node * 64)[f]
                                     : reinterpret_cast<const float4*>(A2 + (size_t)node * 64)[f - 16];
            else        v = reinterpret_cast<const float4*>(A + (size_t)node * K)[f];
            if (SCALE) {
                float s = ns[node];
                v.x *= s; v.y *= s; v.z *= s; v.w *= s;
            }
        }
        uint32_t h0, l0, h1, l1;
        cvt_pair(v.x, v.y, h0, l0);
        cvt_pair(v.z, v.w, h1, l1);
        int o = m * P + f * 2;
        sAh[o] = h0; sAh[o + 1] = h1;
        sAl[o] = l0; sAl[o + 1] = l1;
    }

    // ---- stage B = W^T: pair (n, kp) needs W[2kp][n], W[2kp+1][n] (coalesced over n)
    for (int idx = tid; idx < 64 * (K / 2); idx += 256) {
        int n = idx & 63, kp = idx >> 6;
        float f0 = W[(size_t)(2 * kp)     * 64 + n];
        float f1 = W[(size_t)(2 * kp + 1) * 64 + n];
        uint32_t h, l;
        cvt_pair(f0, f1, h, l);
        int o = n * P + kp;
        sBh[o] = h; sBl[o] = l;
    }
    __syncthreads();

    // ---- compute: per warp, rows 16*wid + {gid, gid+8}, 8 n-tiles
    float acc[8][4];
#pragma unroll
    for (int nt = 0; nt < 8; nt++)
#pragma unroll
        for (int j = 0; j < 4; j++) acc[nt][j] = 0.f;

    const int r0 = wid * 16 + gid;
#pragma unroll
    for (int ks = 0; ks < K / 16; ks++) {
        int kb = ks * 8;                    // pair offset of this k-step
        uint32_t ah[4], al[4];
        ah[0] = sAh[ r0      * P + kb + t];
        ah[1] = sAh[(r0 + 8) * P + kb + t];
        ah[2] = sAh[ r0      * P + kb + 4 + t];
        ah[3] = sAh[(r0 + 8) * P + kb + 4 + t];
        al[0] = sAl[ r0      * P + kb + t];
        al[1] = sAl[(r0 + 8) * P + kb + t];
        al[2] = sAl[ r0      * P + kb + 4 + t];
        al[3] = sAl[(r0 + 8) * P + kb + 4 + t];
#pragma unroll
        for (int nt = 0; nt < 8; nt++) {
            int n = nt * 8 + gid;
            uint32_t bh[2], bl[2];
            bh[0] = sBh[n * P + kb + t];
            bh[1] = sBh[n * P + kb + 4 + t];
            bl[0] = sBl[n * P + kb + t];
            bl[1] = sBl[n * P + kb + 4 + t];
            mma_bf16(acc[nt], ah, bh);
            mma_bf16(acc[nt], ah, bl);
            mma_bf16(acc[nt], al, bh);
        }
    }

    // ---- epilogue: lane covers (row0, cols nt*8+t*2+{0,1}) and (row0+8, same)
    const int node0 = n0 + r0;
    const int node1 = node0 + 8;
    float d0 = 0.f, d1 = 0.f;
    if (EPI == 1) {
        if (node0 < N) d0 = nd[node0];
        if (node1 < N) d1 = nd[node1];
    }
#pragma unroll
    for (int nt = 0; nt < 8; nt++) {
        int col = nt * 8 + t * 2;
        if (EPI == 1) {
            float2 bb = *reinterpret_cast<const float2*>(bias + col);
            if (node0 < N) {
                float2 v;
                v.x = fmaxf(fmaf(acc[nt][0], d0, bb.x), 0.f);
                v.y = fmaxf(fmaf(acc[nt][1], d0, bb.y), 0.f);
                *reinterpret_cast<float2*>(out + (size_t)node0 * 64 + col) = v;
            }
            if (node1 < N) {
                float2 v;
                v.x = fmaxf(fmaf(acc[nt][2], d1, bb.x), 0.f);
                v.y = fmaxf(fmaf(acc[nt][3], d1, bb.y), 0.f);
                *reinterpret_cast<float2*>(out + (size_t)node1 * 64 + col) = v;
            }
        } else {
            if (node0 < N)
                *reinterpret_cast<float2*>(out + (size_t)node0 * 64 + col) =
                    make_float2(acc[nt][0], acc[nt][1]);
            if (node1 < N)
                *reinterpret_cast<float2*>(out + (size_t)node1 * 64 + col) =
                    make_float2(acc[nt][2], acc[nt][3]);
        }
    }
}

// ---------------- pull aggregation: one warp per destination node ----------------
template<int EPI>
__global__ void __launch_bounds__(256)
pull64_kernel(const float* __restrict__ tab,
              const int* __restrict__ rowptr, const int* __restrict__ colidx,
              const float* __restrict__ ns, const float* __restrict__ nd,
              const float* __restrict__ b,
              float* __restrict__ o1, float* __restrict__ o2, int N) {
    int node = (blockIdx.x * blockDim.x + threadIdx.x) >> 5;
    if (node >= N) return;
    const int lane = threadIdx.x & 31;
    const int half = lane >> 4;
    const int q    = lane & 15;
    const int beg = __ldg(&rowptr[node]);
    const int deg = __ldg(&rowptr[node + 1]) - beg;

    float4 acc = make_float4(0.f, 0.f, 0.f, 0.f);

    int i = 0;
    while (i < deg) {
        int rem   = deg - i;
        int chunk = (rem < 32) ? rem : 32;
        int my = __ldg(&colidx[beg + i + ((lane < chunk) ? lane : 0)]);
        int npairs = (chunk + 1) >> 1;
#pragma unroll 4
        for (int p = 0; p < npairs; p++) {
            int j = 2 * p + half;
            bool act = (j < chunk);
            int s = __shfl_sync(0xffffffffu, my, act ? j : 0);
            float4 v = reinterpret_cast<const float4*>(tab + (size_t)s * 64)[q];
            if (act) { acc.x += v.x; acc.y += v.y; acc.z += v.z; acc.w += v.w; }
        }
        i += chunk;
    }

    acc.x += __shfl_xor_sync(0xffffffffu, acc.x, 16);
    acc.y += __shfl_xor_sync(0xffffffffu, acc.y, 16);
    acc.z += __shfl_xor_sync(0xffffffffu, acc.z, 16);
    acc.w += __shfl_xor_sync(0xffffffffu, acc.w, 16);

    if (half != 0) return;

    if (EPI == 0) {
        reinterpret_cast<float4*>(o1 + (size_t)node * 64)[q] = acc;
    } else if (EPI == 1) {
        float d = nd[node];
        float4 bb = reinterpret_cast<const float4*>(b)[q];
        float4 h;
        h.x = fmaxf(fmaf(acc.x, d, bb.x), 0.f);
        h.y = fmaxf(fmaf(acc.y, d, bb.y), 0.f);
        h.z = fmaxf(fmaf(acc.z, d, bb.z), 0.f);
        h.w = fmaxf(fmaf(acc.w, d, bb.w), 0.f);
        reinterpret_cast<float4*>(o1 + (size_t)node * 64)[q] = h;
        float sn = ns[node];
        float4 hn = make_float4(h.x * sn, h.y * sn, h.z * sn, h.w * sn);
        reinterpret_cast<float4*>(o2 + (size_t)node * 64)[q] = hn;
    } else {
        float4 bb = reinterpret_cast<const float4*>(b)[q];
        acc.x += bb.x; acc.y += bb.y; acc.z += bb.z; acc.w += bb.w;
        reinterpret_cast<float4*>(o1 + (size_t)node * 64)[q] = acc;
    }
}

// ---------------- launch ----------------

extern "C" void kernel_launch(void* const* d_in, const int* in_sizes, int n_in,
                              void* d_out, int out_size) {
    const float* feats = (const float*)d_in[0];
    const int*   src   = (const int*)  d_in[1];
    const int*   dst   = (const int*)  d_in[2];
    const float* W1    = (const float*)d_in[3];
    const float* b1    = (const float*)d_in[4];
    const float* W2    = (const float*)d_in[5];
    const float* b2    = (const float*)d_in[6];
    const float* Wout  = (const float*)d_in[7];
    const float* bout  = (const float*)d_in[8];
    float* out = (float*)d_out;

    const int N = in_sizes[0] / 128;
    const int E = in_sizes[1];

    int *p_degin, *p_degout, *p_rowptr, *p_cursor, *p_bsum, *p_colidx;
    float *p_ns, *p_nd, *p_pre, *p_h1, *p_h1n, *p_agg, *p_h2, *p_y;
    cudaGetSymbolAddress((void**)&p_degin,  g_degin);
    cudaGetSymbolAddress((void**)&p_degout, g_degout);
    cudaGetSymbolAddress((void**)&p_rowptr, g_rowptr);
    cudaGetSymbolAddress((void**)&p_cursor, g_cursor);
    cudaGetSymbolAddress((void**)&p_bsum,   g_bsum);
    cudaGetSymbolAddress((void**)&p_colidx, g_colidx);
    cudaGetSymbolAddress((void**)&p_ns,     g_ns);
    cudaGetSymbolAddress((void**)&p_nd,     g_nd);
    cudaGetSymbolAddress((void**)&p_pre,    g_pre);
    cudaGetSymbolAddress((void**)&p_h1,     g_h1);
    cudaGetSymbolAddress((void**)&p_h1n,    g_h1n);
    cudaGetSymbolAddress((void**)&p_agg,    g_agg);
    cudaGetSymbolAddress((void**)&p_h2,     g_h2);
    cudaGetSymbolAddress((void**)&p_y,      g_y);

    const int TB = 256;
    auto cdiv = [](long long a, long long b) { return (unsigned)((a + b - 1) / b); };
    const int nb = (int)cdiv(N, 512);

    // dynamic smem: 384 * P * 4 bytes
    const int SMEM_K128 = 384 * (128 / 2 + 4) * 4;   // 104448
    const int SMEM_K64  = 384 * (64 / 2 + 4)  * 4;   // 55296
    cudaFuncSetAttribute(mma_gemm_kernel<128, true,  false, 0>,
                         cudaFuncAttributeMaxDynamicSharedMemorySize, SMEM_K128);
    cudaFuncSetAttribute(mma_gemm_kernel<64,  false, false, 1>,
                         cudaFuncAttributeMaxDynamicSharedMemorySize, SMEM_K64);
    cudaFuncSetAttribute(mma_gemm_kernel<128, false, true,  0>,
                         cudaFuncAttributeMaxDynamicSharedMemorySize, SMEM_K128);

    // ---- degrees + norms
    zero_deg_kernel<<<cdiv(N, TB), TB>>>(p_degin, p_degout, N);
    degree_kernel  <<<cdiv(E, TB), TB>>>(src, dst, p_degout, p_degin, E);
    norm_kernel    <<<cdiv(N, TB), TB>>>(p_degout, p_degin, p_ns, p_nd, N);

    // ---- CSR by destination
    scan1_kernel<<<nb, 512>>>(p_degin, p_rowptr, p_bsum, N);
    scan2_kernel<<<1, 256>>>(p_bsum, nb);
    scan3_kernel<<<cdiv(N, TB), TB>>>(p_rowptr, p_cursor, p_bsum, N, E);
    csrfill_kernel<<<cdiv(E, TB), TB>>>(src, dst, p_cursor, p_colidx, E);

    const unsigned mmaGrid  = cdiv(N, 128);
    const unsigned pullGrid = cdiv((long long)N * 32, TB);

    // ---- layer 1: pre = (feats*ns)@W1; h1 = relu(pull(pre)*nd + b1); h1n = h1*ns
    mma_gemm_kernel<128, true, false, 0><<<mmaGrid, TB, SMEM_K128>>>(
        feats, nullptr, W1, p_ns, nullptr, nullptr, p_pre, N);
    pull64_kernel<1><<<pullGrid, TB>>>(p_pre, p_rowptr, p_colidx, p_ns, p_nd, b1, p_h1, p_h1n, N);

    // ---- layer 2: agg = pull(h1n); h2 = relu((agg@W2)*nd + b2)
    pull64_kernel<0><<<pullGrid, TB>>>(p_h1n, p_rowptr, p_colidx, nullptr, nullptr, nullptr, p_agg, nullptr, N);
    mma_gemm_kernel<64, false, false, 1><<<mmaGrid, TB, SMEM_K64>>>(
        p_agg, nullptr, W2, nullptr, p_nd, b2, p_h2, N);

    // ---- output: y = [h1|h2]@Wout; out = pull(y) + bout
    mma_gemm_kernel<128, false, true, 0><<<mmaGrid, TB, SMEM_K128>>>(
        p_h1, p_h2, Wout, nullptr, nullptr, nullptr, p_y, N);
    pull64_kernel<2><<<pullGrid, TB>>>(p_y, p_rowptr, p_colidx, nullptr, nullptr, bout, out, nullptr, N);
}

// round 9
// speedup vs baseline: 3.0171x; 1.0480x over previous
#include <cuda_runtime.h>
#include <cuda_bf16.h>
#include <cuda_fp16.h>
#include <cstdint>

#define NMAX 100000
#define EMAX 1600000

// ---------------- scratch (static device globals; no allocation) ----------------
__device__ int   g_degin [NMAX];
__device__ int   g_degout[NMAX];
__device__ float g_ns[NMAX];
__device__ float g_nd[NMAX];
__device__ int   g_rowptr[NMAX + 1];
__device__ int   g_cursor[NMAX];
__device__ int   g_bsum[256];
__device__ int   g_colidx[EMAX];
__device__ __align__(256) __half g_preh[NMAX * 64];   // fp16 pull payloads
__device__ __align__(256) __half g_h1nh[NMAX * 64];
__device__ __align__(256) __half g_yh  [NMAX * 64];
__device__ __align__(256) float  g_h1  [NMAX * 64];   // fp32 GEMM inputs
__device__ __align__(256) float  g_agg [NMAX * 64];
__device__ __align__(256) float  g_h2  [NMAX * 64];

// pack two floats -> fp16x2 in a uint32
__device__ __forceinline__ uint32_t pack_h2(float a, float b) {
    uint32_t lo = (uint32_t)__half_as_ushort(__float2half_rn(a));
    uint32_t hi = (uint32_t)__half_as_ushort(__float2half_rn(b));
    return lo | (hi << 16);
}

// ---------------- small kernels ----------------

__global__ void zero_deg_kernel(int* __restrict__ a, int* __restrict__ b, int N) {
    int i = blockIdx.x * blockDim.x + threadIdx.x;
    if (i < N) { a[i] = 0; b[i] = 0; }
}

__global__ void degree_kernel(const int* __restrict__ src, const int* __restrict__ dst,
                              int* __restrict__ dout, int* __restrict__ din, int E) {
    int e = blockIdx.x * blockDim.x + threadIdx.x;
    if (e >= E) return;
    atomicAdd(&dout[src[e]], 1);
    atomicAdd(&din [dst[e]], 1);
}

__global__ void norm_kernel(const int* __restrict__ dout, const int* __restrict__ din,
                            float* __restrict__ ns, float* __restrict__ nd, int N) {
    int i = blockIdx.x * blockDim.x + threadIdx.x;
    if (i >= N) return;
    ns[i] = rsqrtf((float)max(dout[i], 1));
    nd[i] = rsqrtf((float)max(din [i], 1));
}

__global__ void scan1_kernel(const int* __restrict__ deg, int* __restrict__ rowptr,
                             int* __restrict__ bsum, int N) {
    __shared__ int s[512];
    int t = threadIdx.x;
    int i = blockIdx.x * 512 + t;
    int v = (i < N) ? deg[i] : 0;
    s[t] = v; __syncthreads();
    for (int off = 1; off < 512; off <<= 1) {
        int u = (t >= off) ? s[t - off] : 0;
        __syncthreads();
        s[t] += u;
        __syncthreads();
    }
    if (i < N) rowptr[i] = s[t] - v;
    if (t == 511) bsum[blockIdx.x] = s[511];
}

__global__ void scan2_kernel(int* __restrict__ bsum, int nb) {
    __shared__ int s[256];
    int t = threadIdx.x;
    int v = (t < nb) ? bsum[t] : 0;
    s[t] = v; __syncthreads();
    for (int off = 1; off < 256; off <<= 1) {
        int u = (t >= off) ? s[t - off] : 0;
        __syncthreads();
        s[t] += u;
        __syncthreads();
    }
    if (t < nb) bsum[t] = s[t] - v;
}

__global__ void scan3_kernel(int* __restrict__ rowptr, int* __restrict__ cursor,
                             const int* __restrict__ bsum, int N, int E) {
    int i = blockIdx.x * blockDim.x + threadIdx.x;
    if (i < N) {
        int r = rowptr[i] + bsum[i >> 9];
        rowptr[i] = r;
        cursor[i] = r;
    }
    if (i == 0) rowptr[N] = E;
}

__global__ void csrfill_kernel(const int* __restrict__ src, const int* __restrict__ dst,
                               int* __restrict__ cursor, int* __restrict__ colidx, int E) {
    int e = blockIdx.x * blockDim.x + threadIdx.x;
    if (e >= E) return;
    int slot = atomicAdd(&cursor[dst[e]], 1);
    colidx[slot] = src[e];
}

// ================= split-bf16 mma.sync GEMM (compute_100-legal) =================

__device__ __forceinline__ void mma_bf16(float* c, const uint32_t* a, const uint32_t* b) {
    asm volatile(
        "mma.sync.aligned.m16n8k16.row.col.f32.bf16.bf16.f32 "
        "{%0,%1,%2,%3}, {%4,%5,%6,%7}, {%8,%9}, {%0,%1,%2,%3};"
        : "+f"(c[0]), "+f"(c[1]), "+f"(c[2]), "+f"(c[3])
        : "r"(a[0]), "r"(a[1]), "r"(a[2]), "r"(a[3]), "r"(b[0]), "r"(b[1]));
}

__device__ __forceinline__ void cvt_pair(float f0, float f1, uint32_t& hi, uint32_t& lo) {
    __nv_bfloat16 h0 = __float2bfloat16(f0);
    __nv_bfloat16 h1 = __float2bfloat16(f1);
    __nv_bfloat16 l0 = __float2bfloat16(f0 - __bfloat162float(h0));
    __nv_bfloat16 l1 = __float2bfloat16(f1 - __bfloat162float(h1));
    hi = (uint32_t)__bfloat16_as_ushort(h0) | ((uint32_t)__bfloat16_as_ushort(h1) << 16);
    lo = (uint32_t)__bfloat16_as_ushort(l0) | ((uint32_t)__bfloat16_as_ushort(l1) << 16);
}

// out[N,64] = A[N,K](*ns opt / concat opt) @ W[K,64].
// EPI: 0 plain; 1 relu(v*nd[row]+bias[col]). OUT_HALF: store as fp16 table.
template<int K, bool SCALE, bool CONCAT, int EPI, bool OUT_HALF>
__global__ void __launch_bounds__(256)
mma_gemm_kernel(const float* __restrict__ A, const float* __restrict__ A2,
                const float* __restrict__ W,
                const float* __restrict__ ns, const float* __restrict__ nd,
                const float* __restrict__ bias,
                void* __restrict__ outv, int N) {
    extern __shared__ uint32_t sm[];
    constexpr int P  = K / 2 + 4;
    constexpr int K4 = K / 4;
    uint32_t* sAh = sm;
    uint32_t* sAl = sm + 128 * P;
    uint32_t* sBh = sm + 256 * P;
    uint32_t* sBl = sm + 256 * P + 64 * P;

    const int tid = threadIdx.x;
    const int wid = tid >> 5, lane = tid & 31;
    const int gid = lane >> 2, t = lane & 3;
    const int n0 = blockIdx.x * 128;

    for (int idx = tid; idx < 128 * K4; idx += 256) {
        int m = idx / K4, f = idx % K4;
        int node = n0 + m;
        float4 v = make_float4(0.f, 0.f, 0.f, 0.f);
        if (node < N) {
            if (CONCAT) v = (f < 16) ? reinterpret_cast<const float4*>(A  + (size_t)node * 64)[f]
                                     : reinterpret_cast<const float4*>(A2 + (size_t)node * 64)[f - 16];
            else        v = reinterpret_cast<const float4*>(A + (size_t)node * K)[f];
            if (SCALE) {
                float s = ns[node];
                v.x *= s; v.y *= s; v.z *= s; v.w *= s;
            }
        }
        uint32_t h0, l0, h1, l1;
        cvt_pair(v.x, v.y, h0, l0);
        cvt_pair(v.z, v.w, h1, l1);
        int o = m * P + f * 2;
        sAh[o] = h0; sAh[o + 1] = h1;
        sAl[o] = l0; sAl[o + 1] = l1;
    }

    for (int idx = tid; idx < 64 * (K / 2); idx += 256) {
        int n = idx & 63, kp = idx >> 6;
        float f0 = W[(size_t)(2 * kp)     * 64 + n];
        float f1 = W[(size_t)(2 * kp + 1) * 64 + n];
        uint32_t h, l;
        cvt_pair(f0, f1, h, l);
        int o = n * P + kp;
        sBh[o] = h; sBl[o] = l;
    }
    __syncthreads();

    float acc[8][4];
#pragma unroll
    for (int nt = 0; nt < 8; nt++)
#pragma unroll
        for (int j = 0; j < 4; j++) acc[nt][j] = 0.f;

    const int r0 = wid * 16 + gid;
#pragma unroll
    for (int ks = 0; ks < K / 16; ks++) {
        int kb = ks * 8;
        uint32_t ah[4], al[4];
        ah[0] = sAh[ r0      * P + kb + t];
        ah[1] = sAh[(r0 + 8) * P + kb + t];
        ah[2] = sAh[ r0      * P + kb + 4 + t];
        ah[3] = sAh[(r0 + 8) * P + kb + 4 + t];
        al[0] = sAl[ r0      * P + kb + t];
        al[1] = sAl[(r0 + 8) * P + kb + t];
        al[2] = sAl[ r0      * P + kb + 4 + t];
        al[3] = sAl[(r0 + 8) * P + kb + 4 + t];
#pragma unroll
        for (int nt = 0; nt < 8; nt++) {
            int n = nt * 8 + gid;
            uint32_t bh[2], bl[2];
            bh[0] = sBh[n * P + kb + t];
            bh[1] = sBh[n * P + kb + 4 + t];
            bl[0] = sBl[n * P + kb + t];
            bl[1] = sBl[n * P + kb + 4 + t];
            mma_bf16(acc[nt], ah, bh);
            mma_bf16(acc[nt], ah, bl);
            mma_bf16(acc[nt], al, bh);
        }
    }

    const int node0 = n0 + r0;
    const int node1 = node0 + 8;
    float d0 = 0.f, d1 = 0.f;
    if (EPI == 1) {
        if (node0 < N) d0 = nd[node0];
        if (node1 < N) d1 = nd[node1];
    }
#pragma unroll
    for (int nt = 0; nt < 8; nt++) {
        int col = nt * 8 + t * 2;
        float v0x = acc[nt][0], v0y = acc[nt][1];
        float v1x = acc[nt][2], v1y = acc[nt][3];
        if (EPI == 1) {
            float2 bb = *reinterpret_cast<const float2*>(bias + col);
            v0x = fmaxf(fmaf(v0x, d0, bb.x), 0.f);
            v0y = fmaxf(fmaf(v0y, d0, bb.y), 0.f);
            v1x = fmaxf(fmaf(v1x, d1, bb.x), 0.f);
            v1y = fmaxf(fmaf(v1y, d1, bb.y), 0.f);
        }
        if (OUT_HALF) {
            __half* oh = (__half*)outv;
            if (node0 < N)
                *reinterpret_cast<uint32_t*>(oh + (size_t)node0 * 64 + col) = pack_h2(v0x, v0y);
            if (node1 < N)
                *reinterpret_cast<uint32_t*>(oh + (size_t)node1 * 64 + col) = pack_h2(v1x, v1y);
        } else {
            float* of = (float*)outv;
            if (node0 < N)
                *reinterpret_cast<float2*>(of + (size_t)node0 * 64 + col) = make_float2(v0x, v0y);
            if (node1 < N)
                *reinterpret_cast<float2*>(of + (size_t)node1 * 64 + col) = make_float2(v1x, v1y);
        }
    }
}

// ---------------- fp16-payload pull: one warp/node, quarter-warp per edge row ----------------
// lane = grp*8 + q; edge row = 64 halves = 128B; group reads via q-th uint4 (8 halves).
// EPI: 0 = fp32 store to o1 (agg)
//      1 = h = relu(acc*nd + b); o1 = h (fp32, GEMM input); o2 = (h*ns) fp16 payload
//      2 = o1 = acc + b (fp32 output)
template<int EPI>
__global__ void __launch_bounds__(256)
pull_h16_kernel(const __half* __restrict__ tab,
                const int* __restrict__ rowptr, const int* __restrict__ colidx,
                const float* __restrict__ ns, const float* __restrict__ nd,
                const float* __restrict__ b,
                float* __restrict__ o1, __half* __restrict__ o2, int N) {
    int node = (blockIdx.x * blockDim.x + threadIdx.x) >> 5;
    if (node >= N) return;
    const int lane = threadIdx.x & 31;
    const int grp = lane >> 3;      // which edge of the quad this lane serves
    const int q   = lane & 7;       // uint4 slot within the 64-half row
    const int beg = __ldg(&rowptr[node]);
    const int deg = __ldg(&rowptr[node + 1]) - beg;

    float acc[8];
#pragma unroll
    for (int j = 0; j < 8; j++) acc[j] = 0.f;

    int i = 0;
    while (i < deg) {
        int rem   = deg - i;
        int chunk = (rem < 32) ? rem : 32;
        int my = __ldg(&colidx[beg + i + ((lane < chunk) ? lane : 0)]);
        int nq = (chunk + 3) >> 2;
#pragma unroll 4
        for (int p = 0; p < nq; p++) {
            int j = 4 * p + grp;
            bool act = (j < chunk);
            int s = __shfl_sync(0xffffffffu, my, act ? j : 0);
            uint4 v = *reinterpret_cast<const uint4*>(tab + (size_t)s * 64 + q * 8);
            if (act) {
                const __half2* hp = reinterpret_cast<const __half2*>(&v);
                float2 f0 = __half22float2(hp[0]);
                float2 f1 = __half22float2(hp[1]);
                float2 f2 = __half22float2(hp[2]);
                float2 f3 = __half22float2(hp[3]);
                acc[0] += f0.x; acc[1] += f0.y;
                acc[2] += f1.x; acc[3] += f1.y;
                acc[4] += f2.x; acc[5] += f2.y;
                acc[6] += f3.x; acc[7] += f3.y;
            }
        }
        i += chunk;
    }

    // combine the 4 groups (same q -> same columns)
#pragma unroll
    for (int j = 0; j < 8; j++) {
        acc[j] += __shfl_xor_sync(0xffffffffu, acc[j], 8);
        acc[j] += __shfl_xor_sync(0xffffffffu, acc[j], 16);
    }
    if (grp != 0) return;

    float* o1p = o1 + (size_t)node * 64 + q * 8;
    if (EPI == 0) {
        reinterpret_cast<float4*>(o1p)[0] = make_float4(acc[0], acc[1], acc[2], acc[3]);
        reinterpret_cast<float4*>(o1p)[1] = make_float4(acc[4], acc[5], acc[6], acc[7]);
    } else if (EPI == 1) {
        float d = nd[node];
        float4 b0 = reinterpret_cast<const float4*>(b + q * 8)[0];
        float4 b1 = reinterpret_cast<const float4*>(b + q * 8)[1];
        float h[8];
        h[0] = fmaxf(fmaf(acc[0], d, b0.x), 0.f);
        h[1] = fmaxf(fmaf(acc[1], d, b0.y), 0.f);
        h[2] = fmaxf(fmaf(acc[2], d, b0.z), 0.f);
        h[3] = fmaxf(fmaf(acc[3], d, b0.w), 0.f);
        h[4] = fmaxf(fmaf(acc[4], d, b1.x), 0.f);
        h[5] = fmaxf(fmaf(acc[5], d, b1.y), 0.f);
        h[6] = fmaxf(fmaf(acc[6], d, b1.z), 0.f);
        h[7] = fmaxf(fmaf(acc[7], d, b1.w), 0.f);
        reinterpret_cast<float4*>(o1p)[0] = make_float4(h[0], h[1], h[2], h[3]);
        reinterpret_cast<float4*>(o1p)[1] = make_float4(h[4], h[5], h[6], h[7]);
        float sn = ns[node];
        uint4 pk;
        pk.x = pack_h2(h[0] * sn, h[1] * sn);
        pk.y = pack_h2(h[2] * sn, h[3] * sn);
        pk.z = pack_h2(h[4] * sn, h[5] * sn);
        pk.w = pack_h2(h[6] * sn, h[7] * sn);
        *reinterpret_cast<uint4*>(o2 + (size_t)node * 64 + q * 8) = pk;
    } else {
        float4 b0 = reinterpret_cast<const float4*>(b + q * 8)[0];
        float4 b1 = reinterpret_cast<const float4*>(b + q * 8)[1];
        reinterpret_cast<float4*>(o1p)[0] =
            make_float4(acc[0] + b0.x, acc[1] + b0.y, acc[2] + b0.z, acc[3] + b0.w);
        reinterpret_cast<float4*>(o1p)[1] =
            make_float4(acc[4] + b1.x, acc[5] + b1.y, acc[6] + b1.z, acc[7] + b1.w);
    }
}

// ---------------- launch ----------------

extern "C" void kernel_launch(void* const* d_in, const int* in_sizes, int n_in,
                              void* d_out, int out_size) {
    const float* feats = (const float*)d_in[0];
    const int*   src   = (const int*)  d_in[1];
    const int*   dst   = (const int*)  d_in[2];
    const float* W1    = (const float*)d_in[3];
    const float* b1    = (const float*)d_in[4];
    const float* W2    = (const float*)d_in[5];
    const float* b2    = (const float*)d_in[6];
    const float* Wout  = (const float*)d_in[7];
    const float* bout  = (const float*)d_in[8];
    float* out = (float*)d_out;

    const int N = in_sizes[0] / 128;
    const int E = in_sizes[1];

    int *p_degin, *p_degout, *p_rowptr, *p_cursor, *p_bsum, *p_colidx;
    float *p_ns, *p_nd, *p_h1, *p_agg, *p_h2;
    __half *p_preh, *p_h1nh, *p_yh;
    cudaGetSymbolAddress((void**)&p_degin,  g_degin);
    cudaGetSymbolAddress((void**)&p_degout, g_degout);
    cudaGetSymbolAddress((void**)&p_rowptr, g_rowptr);
    cudaGetSymbolAddress((void**)&p_cursor, g_cursor);
    cudaGetSymbolAddress((void**)&p_bsum,   g_bsum);
    cudaGetSymbolAddress((void**)&p_colidx, g_colidx);
    cudaGetSymbolAddress((void**)&p_ns,     g_ns);
    cudaGetSymbolAddress((void**)&p_nd,     g_nd);
    cudaGetSymbolAddress((void**)&p_preh,   g_preh);
    cudaGetSymbolAddress((void**)&p_h1nh,   g_h1nh);
    cudaGetSymbolAddress((void**)&p_yh,     g_yh);
    cudaGetSymbolAddress((void**)&p_h1,     g_h1);
    cudaGetSymbolAddress((void**)&p_agg,    g_agg);
    cudaGetSymbolAddress((void**)&p_h2,     g_h2);

    const int TB = 256;
    auto cdiv = [](long long a, long long b) { return (unsigned)((a + b - 1) / b); };
    const int nb = (int)cdiv(N, 512);

    const int SMEM_K128 = 384 * (128 / 2 + 4) * 4;   // 104448
    const int SMEM_K64  = 384 * (64 / 2 + 4)  * 4;   // 55296
    cudaFuncSetAttribute(mma_gemm_kernel<128, true,  false, 0, true>,
                         cudaFuncAttributeMaxDynamicSharedMemorySize, SMEM_K128);
    cudaFuncSetAttribute(mma_gemm_kernel<64,  false, false, 1, false>,
                         cudaFuncAttributeMaxDynamicSharedMemorySize, SMEM_K64);
    cudaFuncSetAttribute(mma_gemm_kernel<128, false, true,  0, true>,
                         cudaFuncAttributeMaxDynamicSharedMemorySize, SMEM_K128);

    // ---- degrees + norms
    zero_deg_kernel<<<cdiv(N, TB), TB>>>(p_degin, p_degout, N);
    degree_kernel  <<<cdiv(E, TB), TB>>>(src, dst, p_degout, p_degin, E);
    norm_kernel    <<<cdiv(N, TB), TB>>>(p_degout, p_degin, p_ns, p_nd, N);

    // ---- CSR by destination
    scan1_kernel<<<nb, 512>>>(p_degin, p_rowptr, p_bsum, N);
    scan2_kernel<<<1, 256>>>(p_bsum, nb);
    scan3_kernel<<<cdiv(N, TB), TB>>>(p_rowptr, p_cursor, p_bsum, N, E);
    csrfill_kernel<<<cdiv(E, TB), TB>>>(src, dst, p_cursor, p_colidx, E);

    const unsigned mmaGrid  = cdiv(N, 128);
    const unsigned pullGrid = cdiv((long long)N * 32, TB);

    // ---- layer 1: preh = (feats*ns)@W1 (fp16); h1 = relu(pull(preh)*nd + b1); h1nh = (h1*ns) fp16
    mma_gemm_kernel<128, true, false, 0, true><<<mmaGrid, TB, SMEM_K128>>>(
        feats, nullptr, W1, p_ns, nullptr, nullptr, p_preh, N);
    pull_h16_kernel<1><<<pullGrid, TB>>>(p_preh, p_rowptr, p_colidx, p_ns, p_nd, b1, p_h1, p_h1nh, N);

    // ---- layer 2: agg = pull(h1nh); h2 = relu((agg@W2)*nd + b2)
    pull_h16_kernel<0><<<pullGrid, TB>>>(p_h1nh, p_rowptr, p_colidx, nullptr, nullptr, nullptr, p_agg, nullptr, N);
    mma_gemm_kernel<64, false, false, 1, false><<<mmaGrid, TB, SMEM_K64>>>(
        p_agg, nullptr, W2, nullptr, p_nd, b2, p_h2, N);

    // ---- output: yh = [h1|h2]@Wout (fp16); out = pull(yh) + bout
    mma_gemm_kernel<128, false, true, 0, true><<<mmaGrid, TB, SMEM_K128>>>(
        p_h1, p_h2, Wout, nullptr, nullptr, nullptr, p_yh, N);
    pull_h16_kernel<2><<<pullGrid, TB>>>(p_yh, p_rowptr, p_colidx, nullptr, nullptr, bout, out, nullptr, N);
}

// round 11
// speedup vs baseline: 3.2496x; 1.0771x over previous
#include <cuda_runtime.h>
#include <cuda_bf16.h>
#include <cuda_fp16.h>
#include <cstdint>

#define NMAX 100000
#define EMAX 1600000

// ---------------- scratch (static device globals; no allocation) ----------------
__device__ int   g_degin [NMAX];
__device__ int   g_degout[NMAX];
__device__ float g_ns[NMAX];
__device__ float g_nd[NMAX];
__device__ int   g_rowptr[NMAX + 1];
__device__ int   g_cursor[NMAX];
__device__ int   g_bsum[256];
__device__ int   g_colidx[EMAX];
__device__ __align__(256) __half g_preh[NMAX * 64];   // fp16 pull payloads
__device__ __align__(256) __half g_h1nh[NMAX * 64];
__device__ __align__(256) __half g_yh  [NMAX * 64];
__device__ __align__(256) float  g_h1  [NMAX * 64];   // fp32 GEMM inputs
__device__ __align__(256) float  g_agg [NMAX * 64];

// pack two floats -> fp16x2 in a uint32
__device__ __forceinline__ uint32_t pack_h2(float a, float b) {
    uint32_t lo = (uint32_t)__half_as_ushort(__float2half_rn(a));
    uint32_t hi = (uint32_t)__half_as_ushort(__float2half_rn(b));
    return lo | (hi << 16);
}

// ---------------- small kernels ----------------

__global__ void zero_deg_kernel(int* __restrict__ a, int* __restrict__ b, int N) {
    int i = blockIdx.x * blockDim.x + threadIdx.x;
    if (i < N) { a[i] = 0; b[i] = 0; }
}

__global__ void degree_kernel(const int* __restrict__ src, const int* __restrict__ dst,
                              int* __restrict__ dout, int* __restrict__ din, int E) {
    int e = blockIdx.x * blockDim.x + threadIdx.x;
    if (e >= E) return;
    atomicAdd(&dout[src[e]], 1);
    atomicAdd(&din [dst[e]], 1);
}

// block-level exclusive scan of deg_in -> rowptr partials + block sums; fused norm
__global__ void scan1_kernel(const int* __restrict__ degin, const int* __restrict__ degout,
                             int* __restrict__ rowptr, int* __restrict__ bsum,
                             float* __restrict__ ns, float* __restrict__ nd, int N) {
    __shared__ int s[512];
    int t = threadIdx.x;
    int i = blockIdx.x * 512 + t;
    int v = (i < N) ? degin[i] : 0;
    s[t] = v; __syncthreads();
    for (int off = 1; off < 512; off <<= 1) {
        int u = (t >= off) ? s[t - off] : 0;
        __syncthreads();
        s[t] += u;
        __syncthreads();
    }
    if (i < N) {
        rowptr[i] = s[t] - v;                 // exclusive within block
        nd[i] = rsqrtf((float)max(v, 1));
        ns[i] = rsqrtf((float)max(degout[i], 1));
    }
    if (t == 511) bsum[blockIdx.x] = s[511];
}

// finalize rowptr: every block scans the (<=256) block sums locally, applies offset
__global__ void scan3_kernel(int* __restrict__ rowptr, int* __restrict__ cursor,
                             const int* __restrict__ bsum, int nb, int N, int E) {
    __shared__ int sb[256];
    int t = threadIdx.x;
    int v = (t < nb) ? bsum[t] : 0;
    sb[t] = v; __syncthreads();
    for (int off = 1; off < 256; off <<= 1) {
        int u = (t >= off) ? sb[t - off] : 0;
        __syncthreads();
        sb[t] += u;
        __syncthreads();
    }
    int ex = sb[t] - v;                       // exclusive
    __syncthreads();
    sb[t] = ex;
    __syncthreads();
    int i = blockIdx.x * blockDim.x + threadIdx.x;
    if (i < N) {
        int r = rowptr[i] + sb[i >> 9];
        rowptr[i] = r;
        cursor[i] = r;
    }
    if (i == 0) rowptr[N] = E;
}

__global__ void csrfill_kernel(const int* __restrict__ src, const int* __restrict__ dst,
                               int* __restrict__ cursor, int* __restrict__ colidx, int E) {
    int e = blockIdx.x * blockDim.x + threadIdx.x;
    if (e >= E) return;
    int slot = atomicAdd(&cursor[dst[e]], 1);
    colidx[slot] = src[e];
}

// ================= split-bf16 mma.sync GEMM pieces (compute_100-legal) =================

__device__ __forceinline__ void mma_bf16(float* c, const uint32_t* a, const uint32_t* b) {
    asm volatile(
        "mma.sync.aligned.m16n8k16.row.col.f32.bf16.bf16.f32 "
        "{%0,%1,%2,%3}, {%4,%5,%6,%7}, {%8,%9}, {%0,%1,%2,%3};"
        : "+f"(c[0]), "+f"(c[1]), "+f"(c[2]), "+f"(c[3])
        : "r"(a[0]), "r"(a[1]), "r"(a[2]), "r"(a[3]), "r"(b[0]), "r"(b[1]));
}

__device__ __forceinline__ void cvt_pair(float f0, float f1, uint32_t& hi, uint32_t& lo) {
    __nv_bfloat16 h0 = __float2bfloat16(f0);
    __nv_bfloat16 h1 = __float2bfloat16(f1);
    __nv_bfloat16 l0 = __float2bfloat16(f0 - __bfloat162float(h0));
    __nv_bfloat16 l1 = __float2bfloat16(f1 - __bfloat162float(h1));
    hi = (uint32_t)__bfloat16_as_ushort(h0) | ((uint32_t)__bfloat16_as_ushort(h1) << 16);
    lo = (uint32_t)__bfloat16_as_ushort(l0) | ((uint32_t)__bfloat16_as_ushort(l1) << 16);
}

// layer-1 GEMM: preh[N,64] = fp16( (feats*ns)[N,128] @ W1[128,64] )
__global__ void __launch_bounds__(256)
gemm1_kernel(const float* __restrict__ A, const float* __restrict__ W,
             const float* __restrict__ ns, __half* __restrict__ outh, int N) {
    extern __shared__ uint32_t sm[];
    constexpr int K = 128, P = K / 2 + 4, K4 = K / 4;
    uint32_t* sAh = sm;
    uint32_t* sAl = sm + 128 * P;
    uint32_t* sBh = sm + 256 * P;
    uint32_t* sBl = sm + 256 * P + 64 * P;

    const int tid = threadIdx.x;
    const int wid = tid >> 5, lane = tid & 31;
    const int gid = lane >> 2, t = lane & 3;
    const int n0 = blockIdx.x * 128;

    for (int idx = tid; idx < 128 * K4; idx += 256) {
        int m = idx / K4, f = idx % K4;
        int node = n0 + m;
        float4 v = make_float4(0.f, 0.f, 0.f, 0.f);
        if (node < N) {
            v = reinterpret_cast<const float4*>(A + (size_t)node * K)[f];
            float s = ns[node];
            v.x *= s; v.y *= s; v.z *= s; v.w *= s;
        }
        uint32_t h0, l0, h1, l1;
        cvt_pair(v.x, v.y, h0, l0);
        cvt_pair(v.z, v.w, h1, l1);
        int o = m * P + f * 2;
        sAh[o] = h0; sAh[o + 1] = h1;
        sAl[o] = l0; sAl[o + 1] = l1;
    }
    for (int idx = tid; idx < 64 * (K / 2); idx += 256) {
        int n = idx & 63, kp = idx >> 6;
        uint32_t h, l;
        cvt_pair(W[(size_t)(2 * kp) * 64 + n], W[(size_t)(2 * kp + 1) * 64 + n], h, l);
        sBh[n * P + kp] = h; sBl[n * P + kp] = l;
    }
    __syncthreads();

    float acc[8][4];
#pragma unroll
    for (int nt = 0; nt < 8; nt++)
#pragma unroll
        for (int j = 0; j < 4; j++) acc[nt][j] = 0.f;

    const int r0 = wid * 16 + gid;
#pragma unroll
    for (int ks = 0; ks < K / 16; ks++) {
        int kb = ks * 8;
        uint32_t ah[4], al[4];
        ah[0] = sAh[ r0      * P + kb + t];
        ah[1] = sAh[(r0 + 8) * P + kb + t];
        ah[2] = sAh[ r0      * P + kb + 4 + t];
        ah[3] = sAh[(r0 + 8) * P + kb + 4 + t];
        al[0] = sAl[ r0      * P + kb + t];
        al[1] = sAl[(r0 + 8) * P + kb + t];
        al[2] = sAl[ r0      * P + kb + 4 + t];
        al[3] = sAl[(r0 + 8) * P + kb + 4 + t];
#pragma unroll
        for (int nt = 0; nt < 8; nt++) {
            int n = nt * 8 + gid;
            uint32_t bh[2], bl[2];
            bh[0] = sBh[n * P + kb + t];
            bh[1] = sBh[n * P + kb + 4 + t];
            bl[0] = sBl[n * P + kb + t];
            bl[1] = sBl[n * P + kb + 4 + t];
            mma_bf16(acc[nt], ah, bh);
            mma_bf16(acc[nt], ah, bl);
            mma_bf16(acc[nt], al, bh);
        }
    }

    const int node0 = n0 + r0, node1 = node0 + 8;
#pragma unroll
    for (int nt = 0; nt < 8; nt++) {
        int col = nt * 8 + t * 2;
        if (node0 < N)
            *reinterpret_cast<uint32_t*>(outh + (size_t)node0 * 64 + col) = pack_h2(acc[nt][0], acc[nt][1]);
        if (node1 < N)
            *reinterpret_cast<uint32_t*>(outh + (size_t)node1 * 64 + col) = pack_h2(acc[nt][2], acc[nt][3]);
    }
}

// fused layers 2+3: h2 = relu((agg@W2)*nd + b2) [kept in regs];
//                   yh = fp16( [h1|h2] @ Wout )
__global__ void __launch_bounds__(256)
gemm23_kernel(const float* __restrict__ agg, const float* __restrict__ h1,
              const float* __restrict__ W2, const float* __restrict__ b2,
              const float* __restrict__ nd, const float* __restrict__ Wout,
              __half* __restrict__ yh, int N) {
    extern __shared__ uint32_t sm[];
    constexpr int P1 = 64 / 2 + 4;    // 36
    constexpr int P2 = 128 / 2 + 4;   // 68

    const int tid = threadIdx.x;
    const int wid = tid >> 5, lane = tid & 31;
    const int gid = lane >> 2, t = lane & 3;
    const int n0 = blockIdx.x * 128;
    const int r0 = wid * 16 + gid;
    const int node0 = n0 + r0, node1 = node0 + 8;

    // ---------- phase 1: acc = agg @ W2  (K=64) ----------
    {
        uint32_t* sAh = sm;
        uint32_t* sAl = sm + 128 * P1;
        uint32_t* sBh = sm + 256 * P1;
        uint32_t* sBl = sm + 256 * P1 + 64 * P1;

        for (int idx = tid; idx < 128 * 16; idx += 256) {
            int m = idx / 16, f = idx % 16;
            int node = n0 + m;
            float4 v = make_float4(0.f, 0.f, 0.f, 0.f);
            if (node < N) v = reinterpret_cast<const float4*>(agg + (size_t)node * 64)[f];
            uint32_t h0, l0, h1v, l1;
            cvt_pair(v.x, v.y, h0, l0);
            cvt_pair(v.z, v.w, h1v, l1);
            int o = m * P1 + f * 2;
            sAh[o] = h0; sAh[o + 1] = h1v;
            sAl[o] = l0; sAl[o + 1] = l1;
        }
        for (int idx = tid; idx < 64 * 32; idx += 256) {
            int n = idx & 63, kp = idx >> 6;
            uint32_t h, l;
            cvt_pair(W2[(size_t)(2 * kp) * 64 + n], W2[(size_t)(2 * kp + 1) * 64 + n], h, l);
            sBh[n * P1 + kp] = h; sBl[n * P1 + kp] = l;
        }
        __syncthreads();

        float acc[8][4];
#pragma unroll
        for (int nt = 0; nt < 8; nt++)
#pragma unroll
            for (int j = 0; j < 4; j++) acc[nt][j] = 0.f;

#pragma unroll
        for (int ks = 0; ks < 4; ks++) {
            int kb = ks * 8;
            uint32_t ah[4], al[4];
            ah[0] = sAh[ r0      * P1 + kb + t];
            ah[1] = sAh[(r0 + 8) * P1 + kb + t];
            ah[2] = sAh[ r0      * P1 + kb + 4 + t];
            ah[3] = sAh[(r0 + 8) * P1 + kb + 4 + t];
            al[0] = sAl[ r0      * P1 + kb + t];
            al[1] = sAl[(r0 + 8) * P1 + kb + t];
            al[2] = sAl[ r0      * P1 + kb + 4 + t];
            al[3] = sAl[(r0 + 8) * P1 + kb + 4 + t];
#pragma unroll
            for (int nt = 0; nt < 8; nt++) {
                int n = nt * 8 + gid;
                uint32_t bh[2], bl[2];
                bh[0] = sBh[n * P1 + kb + t];
                bh[1] = sBh[n * P1 + kb + 4 + t];
                bl[0] = sBl[n * P1 + kb + t];
                bl[1] = sBl[n * P1 + kb + 4 + t];
                mma_bf16(acc[nt], ah, bh);
                mma_bf16(acc[nt], ah, bl);
                mma_bf16(acc[nt], al, bh);
            }
        }

        // epilogue: h2 = relu(acc*nd + b2), restage into phase-2 A (k = 64+col)
        float d0 = (node0 < N) ? nd[node0] : 0.f;
        float d1 = (node1 < N) ? nd[node1] : 0.f;
        float h2v[8][4];
#pragma unroll
        for (int nt = 0; nt < 8; nt++) {
            int col = nt * 8 + t * 2;
            float2 bb = *reinterpret_cast<const float2*>(b2 + col);
            h2v[nt][0] = fmaxf(fmaf(acc[nt][0], d0, bb.x), 0.f);
            h2v[nt][1] = fmaxf(fmaf(acc[nt][1], d0, bb.y), 0.f);
            h2v[nt][2] = fmaxf(fmaf(acc[nt][2], d1, bb.x), 0.f);
            h2v[nt][3] = fmaxf(fmaf(acc[nt][3], d1, bb.y), 0.f);
        }
        __syncthreads();   // phase-1 smem reads done; safe to overwrite

        // ---------- phase 2 staging ----------
        uint32_t* sAh2 = sm;
        uint32_t* sAl2 = sm + 128 * P2;
        uint32_t* sBh2 = sm + 256 * P2;
        uint32_t* sBl2 = sm + 256 * P2 + 64 * P2;

        // h1 part (k 0..63)
        for (int idx = tid; idx < 128 * 16; idx += 256) {
            int m = idx / 16, f = idx % 16;
            int node = n0 + m;
            float4 v = make_float4(0.f, 0.f, 0.f, 0.f);
            if (node < N) v = reinterpret_cast<const float4*>(h1 + (size_t)node * 64)[f];
            uint32_t h0, l0, h1v, l1;
            cvt_pair(v.x, v.y, h0, l0);
            cvt_pair(v.z, v.w, h1v, l1);
            int o = m * P2 + f * 2;
            sAh2[o] = h0; sAh2[o + 1] = h1v;
            sAl2[o] = l0; sAl2[o + 1] = l1;
        }
        // h2 part from registers (k 64..127 -> kp 32..63)
#pragma unroll
        for (int nt = 0; nt < 8; nt++) {
            int kp = 32 + nt * 4 + t;
            uint32_t h, l;
            cvt_pair(h2v[nt][0], h2v[nt][1], h, l);
            sAh2[r0 * P2 + kp] = h; sAl2[r0 * P2 + kp] = l;
            cvt_pair(h2v[nt][2], h2v[nt][3], h, l);
            sAh2[(r0 + 8) * P2 + kp] = h; sAl2[(r0 + 8) * P2 + kp] = l;
        }
        // B = Wout^T (K=128)
        for (int idx = tid; idx < 64 * 64; idx += 256) {
            int n = idx & 63, kp = idx >> 6;
            uint32_t h, l;
            cvt_pair(Wout[(size_t)(2 * kp) * 64 + n], Wout[(size_t)(2 * kp + 1) * 64 + n], h, l);
            sBh2[n * P2 + kp] = h; sBl2[n * P2 + kp] = l;
        }
        __syncthreads();

        // ---------- phase 2 MMA: y = [h1|h2] @ Wout ----------
#pragma unroll
        for (int nt = 0; nt < 8; nt++)
#pragma unroll
            for (int j = 0; j < 4; j++) acc[nt][j] = 0.f;

#pragma unroll
        for (int ks = 0; ks < 8; ks++) {
            int kb = ks * 8;
            uint32_t ah[4], al[4];
            ah[0] = sAh2[ r0      * P2 + kb + t];
            ah[1] = sAh2[(r0 + 8) * P2 + kb + t];
            ah[2] = sAh2[ r0      * P2 + kb + 4 + t];
            ah[3] = sAh2[(r0 + 8) * P2 + kb + 4 + t];
            al[0] = sAl2[ r0      * P2 + kb + t];
            al[1] = sAl2[(r0 + 8) * P2 + kb + t];
            al[2] = sAl2[ r0      * P2 + kb + 4 + t];
            al[3] = sAl2[(r0 + 8) * P2 + kb + 4 + t];
#pragma unroll
            for (int nt = 0; nt < 8; nt++) {
                int n = nt * 8 + gid;
                uint32_t bh[2], bl[2];
                bh[0] = sBh2[n * P2 + kb + t];
                bh[1] = sBh2[n * P2 + kb + 4 + t];
                bl[0] = sBl2[n * P2 + kb + t];
                bl[1] = sBl2[n * P2 + kb + 4 + t];
                mma_bf16(acc[nt], ah, bh);
                mma_bf16(acc[nt], ah, bl);
                mma_bf16(acc[nt], al, bh);
            }
        }

#pragma unroll
        for (int nt = 0; nt < 8; nt++) {
            int col = nt * 8 + t * 2;
            if (node0 < N)
                *reinterpret_cast<uint32_t*>(yh + (size_t)node0 * 64 + col) = pack_h2(acc[nt][0], acc[nt][1]);
            if (node1 < N)
                *reinterpret_cast<uint32_t*>(yh + (size_t)node1 * 64 + col) = pack_h2(acc[nt][2], acc[nt][3]);
        }
    }
}

// ---------------- fp16-payload pull: one warp/node, quarter-warp per edge row ----------------
// EPI: 0 = fp32 store to o1 (agg)
//      1 = h = relu(acc*nd + b); o1 = h (fp32); o2 = (h*ns) fp16 payload
//      2 = o1 = acc + b (fp32 output)
template<int EPI>
__global__ void __launch_bounds__(256)
pull_h16_kernel(const __half* __restrict__ tab,
                const int* __restrict__ rowptr, const int* __restrict__ colidx,
                const float* __restrict__ ns, const float* __restrict__ nd,
                const float* __restrict__ b,
                float* __restrict__ o1, __half* __restrict__ o2, int N) {
    int node = (blockIdx.x * blockDim.x + threadIdx.x) >> 5;
    if (node >= N) return;
    const int lane = threadIdx.x & 31;
    const int grp = lane >> 3;
    const int q   = lane & 7;
    const int beg = __ldg(&rowptr[node]);
    const int deg = __ldg(&rowptr[node + 1]) - beg;

    float acc[8];
#pragma unroll
    for (int j = 0; j < 8; j++) acc[j] = 0.f;

    int i = 0;
    while (i < deg) {
        int rem   = deg - i;
        int chunk = (rem < 32) ? rem : 32;
        int my = __ldg(&colidx[beg + i + ((lane < chunk) ? lane : 0)]);
        int nq = (chunk + 3) >> 2;
#pragma unroll 4
        for (int p = 0; p < nq; p++) {
            int j = 4 * p + grp;
            bool act = (j < chunk);
            int s = __shfl_sync(0xffffffffu, my, act ? j : 0);
            uint4 v = *reinterpret_cast<const uint4*>(tab + (size_t)s * 64 + q * 8);
            if (act) {
                const __half2* hp = reinterpret_cast<const __half2*>(&v);
                float2 f0 = __half22float2(hp[0]);
                float2 f1 = __half22float2(hp[1]);
                float2 f2 = __half22float2(hp[2]);
                float2 f3 = __half22float2(hp[3]);
                acc[0] += f0.x; acc[1] += f0.y;
                acc[2] += f1.x; acc[3] += f1.y;
                acc[4] += f2.x; acc[5] += f2.y;
                acc[6] += f3.x; acc[7] += f3.y;
            }
        }
        i += chunk;
    }

#pragma unroll
    for (int j = 0; j < 8; j++) {
        acc[j] += __shfl_xor_sync(0xffffffffu, acc[j], 8);
        acc[j] += __shfl_xor_sync(0xffffffffu, acc[j], 16);
    }
    if (grp != 0) return;

    float* o1p = o1 + (size_t)node * 64 + q * 8;
    if (EPI == 0) {
        reinterpret_cast<float4*>(o1p)[0] = make_float4(acc[0], acc[1], acc[2], acc[3]);
        reinterpret_cast<float4*>(o1p)[1] = make_float4(acc[4], acc[5], acc[6], acc[7]);
    } else if (EPI == 1) {
        float d = nd[node];
        float4 b0 = reinterpret_cast<const float4*>(b + q * 8)[0];
        float4 b1 = reinterpret_cast<const float4*>(b + q * 8)[1];
        float h[8];
        h[0] = fmaxf(fmaf(acc[0], d, b0.x), 0.f);
        h[1] = fmaxf(fmaf(acc[1], d, b0.y), 0.f);
        h[2] = fmaxf(fmaf(acc[2], d, b0.z), 0.f);
        h[3] = fmaxf(fmaf(acc[3], d, b0.w), 0.f);
        h[4] = fmaxf(fmaf(acc[4], d, b1.x), 0.f);
        h[5] = fmaxf(fmaf(acc[5], d, b1.y), 0.f);
        h[6] = fmaxf(fmaf(acc[6], d, b1.z), 0.f);
        h[7] = fmaxf(fmaf(acc[7], d, b1.w), 0.f);
        reinterpret_cast<float4*>(o1p)[0] = make_float4(h[0], h[1], h[2], h[3]);
        reinterpret_cast<float4*>(o1p)[1] = make_float4(h[4], h[5], h[6], h[7]);
        float sn = ns[node];
        uint4 pk;
        pk.x = pack_h2(h[0] * sn, h[1] * sn);
        pk.y = pack_h2(h[2] * sn, h[3] * sn);
        pk.z = pack_h2(h[4] * sn, h[5] * sn);
        pk.w = pack_h2(h[6] * sn, h[7] * sn);
        *reinterpret_cast<uint4*>(o2 + (size_t)node * 64 + q * 8) = pk;
    } else {
        float4 b0 = reinterpret_cast<const float4*>(b + q * 8)[0];
        float4 b1 = reinterpret_cast<const float4*>(b + q * 8)[1];
        reinterpret_cast<float4*>(o1p)[0] =
            make_float4(acc[0] + b0.x, acc[1] + b0.y, acc[2] + b0.z, acc[3] + b0.w);
        reinterpret_cast<float4*>(o1p)[1] =
            make_float4(acc[4] + b1.x, acc[5] + b1.y, acc[6] + b1.z, acc[7] + b1.w);
    }
}

// ---------------- launch ----------------

extern "C" void kernel_launch(void* const* d_in, const int* in_sizes, int n_in,
                              void* d_out, int out_size) {
    const float* feats = (const float*)d_in[0];
    const int*   src   = (const int*)  d_in[1];
    const int*   dst   = (const int*)  d_in[2];
    const float* W1    = (const float*)d_in[3];
    const float* b1    = (const float*)d_in[4];
    const float* W2    = (const float*)d_in[5];
    const float* b2    = (const float*)d_in[6];
    const float* Wout  = (const float*)d_in[7];
    const float* bout  = (const float*)d_in[8];
    float* out = (float*)d_out;

    const int N = in_sizes[0] / 128;
    const int E = in_sizes[1];

    int *p_degin, *p_degout, *p_rowptr, *p_cursor, *p_bsum, *p_colidx;
    float *p_ns, *p_nd, *p_h1, *p_agg;
    __half *p_preh, *p_h1nh, *p_yh;
    cudaGetSymbolAddress((void**)&p_degin,  g_degin);
    cudaGetSymbolAddress((void**)&p_degout, g_degout);
    cudaGetSymbolAddress((void**)&p_rowptr, g_rowptr);
    cudaGetSymbolAddress((void**)&p_cursor, g_cursor);
    cudaGetSymbolAddress((void**)&p_bsum,   g_bsum);
    cudaGetSymbolAddress((void**)&p_colidx, g_colidx);
    cudaGetSymbolAddress((void**)&p_ns,     g_ns);
    cudaGetSymbolAddress((void**)&p_nd,     g_nd);
    cudaGetSymbolAddress((void**)&p_preh,   g_preh);
    cudaGetSymbolAddress((void**)&p_h1nh,   g_h1nh);
    cudaGetSymbolAddress((void**)&p_yh,     g_yh);
    cudaGetSymbolAddress((void**)&p_h1,     g_h1);
    cudaGetSymbolAddress((void**)&p_agg,    g_agg);

    const int TB = 256;
    auto cdiv = [](long long a, long long b) { return (unsigned)((a + b - 1) / b); };
    const int nb = (int)cdiv(N, 512);        // <= 256 for N <= 131072

    const int SMEM_BIG = 384 * (128 / 2 + 4) * 4;   // 104448 (K=128 layout)
    cudaFuncSetAttribute(gemm1_kernel,  cudaFuncAttributeMaxDynamicSharedMemorySize, SMEM_BIG);
    cudaFuncSetAttribute(gemm23_kernel, cudaFuncAttributeMaxDynamicSharedMemorySize, SMEM_BIG);

    // 1-5: degrees, norms, CSR
    zero_deg_kernel<<<cdiv(N, TB), TB>>>(p_degin, p_degout, N);
    degree_kernel  <<<cdiv(E, TB), TB>>>(src, dst, p_degout, p_degin, E);
    scan1_kernel   <<<nb, 512>>>(p_degin, p_degout, p_rowptr, p_bsum, p_ns, p_nd, N);
    scan3_kernel   <<<cdiv(N, TB), TB>>>(p_rowptr, p_cursor, p_bsum, nb, N, E);
    csrfill_kernel <<<cdiv(E, TB), TB>>>(src, dst, p_cursor, p_colidx, E);

    const unsigned mmaGrid  = cdiv(N, 128);
    const unsigned pullGrid = cdiv((long long)N * 32, TB);

    // 6: preh = (feats*ns)@W1 (fp16)
    gemm1_kernel<<<mmaGrid, TB, SMEM_BIG>>>(feats, W1, p_ns, p_preh, N);
    // 7: h1 = relu(pull(preh)*nd + b1); h1nh = (h1*ns) fp16
    pull_h16_kernel<1><<<pullGrid, TB>>>(p_preh, p_rowptr, p_colidx, p_ns, p_nd, b1, p_h1, p_h1nh, N);
    // 8: agg = pull(h1nh)
    pull_h16_kernel<0><<<pullGrid, TB>>>(p_h1nh, p_rowptr, p_colidx, nullptr, nullptr, nullptr, p_agg, nullptr, N);
    // 9: h2 = relu((agg@W2)*nd+b2) [regs]; yh = [h1|h2]@Wout (fp16)
    gemm23_kernel<<<mmaGrid, TB, SMEM_BIG>>>(p_agg, p_h1, W2, b2, p_nd, Wout, p_yh, N);
    // 10: out = pull(yh) + bout
    pull_h16_kernel<2><<<pullGrid, TB>>>(p_yh, p_rowptr, p_colidx, nullptr, nullptr, bout, out, nullptr, N);
}